// round 14
// baseline (speedup 1.0000x reference)
#include <cuda_runtime.h>
#include <math.h>

#define LSEQ 9216
#define NCHK 288
#define TCH  32
#define NGRP 18
#define GSZ  16

// ------------------------- scratch (device globals) -------------------------
__device__ __align__(16) float g_Um [4*LSEQ*64];
__device__ __align__(16) float g_Z  [4*LSEQ*64];
__device__ __align__(16) float g_dm [4*LSEQ*64];
__device__ __align__(16) float g_BCm[4*LSEQ*32];
__device__ __align__(16) float g_ym [4*LSEQ*64];
__device__ __align__(16) float g_Ug [4*LSEQ*128];
__device__ __align__(16) float g_dg [4*LSEQ*128];
__device__ __align__(16) float g_BCg[4*LSEQ*32];
__device__ __align__(16) float g_yg [4*LSEQ*128];
__device__ __align__(16) float g_SumM[4*NCHK*64*32];
__device__ __align__(16) float g_SumG[(size_t)4*NCHK*128*32];
__device__ __align__(16) float g_HinM[4*NCHK*64*16];
__device__ __align__(16) float g_HinG[4*NCHK*128*16];
// group-level prefix scratch
__device__ __align__(16) float g_GAm[4*NGRP*64*16];
__device__ __align__(16) float g_GBm[4*NGRP*64*16];
__device__ __align__(16) float g_GHm[4*NGRP*64*16];
__device__ __align__(16) float g_GAg[4*NGRP*128*16];
__device__ __align__(16) float g_GBg[4*NGRP*128*16];
__device__ __align__(16) float g_GHg[4*NGRP*128*16];

__device__ __forceinline__ float siluf(float y) {
    return y / (1.f + __expf(-y));
}
__device__ __forceinline__ float softplusf(float x) {
    return (x > 20.f) ? x : log1pf(expf(x));
}
// pw[k] = e1^(k+1), k=0..15, log-depth multiply tree
__device__ __forceinline__ void powers16(float e1, float* pw) {
    pw[0]=e1;
    pw[1]=pw[0]*pw[0];  pw[2]=pw[1]*pw[0];  pw[3]=pw[1]*pw[1];
    pw[4]=pw[2]*pw[1];  pw[5]=pw[2]*pw[2];  pw[6]=pw[3]*pw[2];  pw[7]=pw[3]*pw[3];
    pw[8]=pw[4]*pw[3];  pw[9]=pw[4]*pw[4];  pw[10]=pw[5]*pw[4]; pw[11]=pw[5]*pw[5];
    pw[12]=pw[6]*pw[5]; pw[13]=pw[6]*pw[6]; pw[14]=pw[7]*pw[6]; pw[15]=pw[7]*pw[7];
}
__device__ __forceinline__ bool loadA(const float* Alog, int d, float* Ar) {
    #pragma unroll
    for (int n = 0; n < 16; n++) Ar[n] = -__expf(Alog[d*16 + n]);
    bool st = true;
    #pragma unroll
    for (int n = 1; n < 16; n++)
        if (fabsf(Ar[n] - (float)(n+1)*Ar[0]) > 1e-4f * fabsf(Ar[n])) st = false;
    return st;
}
// 4-accumulator dot of 64 elements (breaks FFMA dep chain)
__device__ __forceinline__ float dot64(const float4* row, const float* w) {
    float a0=0.f, a1=0.f, a2=0.f, a3=0.f;
    #pragma unroll
    for (int k4 = 0; k4 < 16; k4 += 4) {
        float4 v0 = row[k4],   v1 = row[k4+1];
        float4 v2 = row[k4+2], v3 = row[k4+3];
        a0 += v0.x*w[4*k4+0]  + v0.y*w[4*k4+1]  + v0.z*w[4*k4+2]  + v0.w*w[4*k4+3];
        a1 += v1.x*w[4*k4+4]  + v1.y*w[4*k4+5]  + v1.z*w[4*k4+6]  + v1.w*w[4*k4+7];
        a2 += v2.x*w[4*k4+8]  + v2.y*w[4*k4+9]  + v2.z*w[4*k4+10] + v2.w*w[4*k4+11];
        a3 += v3.x*w[4*k4+12] + v3.y*w[4*k4+13] + v3.z*w[4*k4+14] + v3.w*w[4*k4+15];
    }
    return (a0 + a1) + (a2 + a3);
}

// ======== mixer front: GEMM + dwconv + silu + FUSED proj/delta ==============
__global__ void __launch_bounds__(128) k_mixer_front(
    const float* __restrict__ f1, const float* __restrict__ f2,
    const float* __restrict__ Wi, const float* __restrict__ bi,
    const float* __restrict__ wcx, const float* __restrict__ bcx,
    const float* __restrict__ wcz, const float* __restrict__ bcz,
    const float* __restrict__ Wxp, const float* __restrict__ Wdt,
    const float* __restrict__ bdt)
{
    const int TF = 64;
    __shared__ __align__(16) float sx[TF+3][64];
    __shared__ __align__(16) float su[TF][68];    // also reused as tmp[64][67]
    __shared__ __align__(16) float swx[36][68];
    __shared__ float sdt[TF][4];
    int s = blockIdx.x;
    const float* f = ((s >> 1) ? f2 : f1) + (size_t)(s & 1) * 64 * LSEQ;
    int l0 = blockIdx.y * TF;
    int tid = threadIdx.x, lane = tid & 31, w4 = tid >> 5;

    // coalesced load: warp per channel row, lanes along sequence
    {
        float (*tmp)[TF+3] = (float(*)[TF+3])su;   // 64 x 67 <= 64 x 68
        for (int r = w4; r < 64; r += 4) {
            const float* fr = f + (size_t)r*LSEQ + l0 - 1;
            #pragma unroll
            for (int j = lane; j < TF+3; j += 32) {
                int gl = l0 - 1 + j;
                tmp[r][j] = (gl >= 0 && gl < LSEQ) ? fr[j] : 0.f;
            }
        }
        for (int i = tid; i < 36*64; i += 128) swx[i >> 6][i & 63] = Wxp[i];
        __syncthreads();
        // transpose tmp[c][j] -> sx[j][c]  (stride 67: conflict-free)
        for (int j = w4; j < TF+3; j += 4) {
            sx[j][lane]      = tmp[lane][j];
            sx[j][lane + 32] = tmp[lane + 32][j];
        }
    }
    __syncthreads();

    int c = tid;
    {
        float w[64];
        #pragma unroll 16
        for (int k = 0; k < 64; k++) w[k] = Wi[c*64 + k];
        float bias = bi[c];
        const float* cw = (c < 64) ? (wcx + c*4) : (wcz + (c-64)*4);
        float cw0 = cw[0], cw1 = cw[1], cw2 = cw[2], cw3 = cw[3];
        float cb = (c < 64) ? bcx[c] : bcz[c-64];
        bool isx = (c < 64);
        float* outp = isx ? (g_Um + (size_t)s*LSEQ*64 + c)
                          : (g_Z  + (size_t)s*LSEQ*64 + (c-64));
        float x0 = 0.f, x1 = 0.f, x2 = 0.f;
        for (int j = 0; j < TF+3; j++) {
            int gl = l0 - 1 + j;
            float acc = bias + dot64((const float4*)sx[j], w);
            if (gl < 0 || gl >= LSEQ) acc = 0.f;
            if (j >= 3) {
                float y = cw0*x0 + cw1*x1 + cw2*x2 + cw3*acc + cb;
                float v = siluf(y);
                outp[(size_t)(l0 + j - 3) * 64] = v;
                if (isx) su[j-3][c] = v;
            }
            x0 = x1; x1 = x2; x2 = acc;
        }
    }
    __syncthreads();

    {
        int q = tid & 3;
        #pragma unroll
        for (int p = 0; p < 2; p++) {
            int t = p*32 + (tid >> 2);
            float accr[9];
            #pragma unroll
            for (int j = 0; j < 9; j++) accr[j] = 0.f;
            const float4* u4 = (const float4*)su[t];
            #pragma unroll
            for (int k4 = 0; k4 < 16; k4++) {
                float4 uv = u4[k4];
                #pragma unroll
                for (int j = 0; j < 9; j++) {
                    float4 wv = ((const float4*)swx[q*9 + j])[k4];
                    accr[j] += uv.x*wv.x + uv.y*wv.y + uv.z*wv.z + uv.w*wv.w;
                }
            }
            #pragma unroll
            for (int j = 0; j < 9; j++) {
                int r = q*9 + j;
                if (r < 4) sdt[t][r] = accr[j];
                else g_BCm[((size_t)s*LSEQ + l0 + t)*32 + (r-4)] = accr[j];
            }
        }
    }
    __syncthreads();

    for (int i = tid; i < TF*64; i += 128) {
        int t = i >> 6, d = i & 63;
        float x = sdt[t][0]*Wdt[d*4]   + sdt[t][1]*Wdt[d*4+1]
                + sdt[t][2]*Wdt[d*4+2] + sdt[t][3]*Wdt[d*4+3] + bdt[d];
        g_dm[((size_t)s*LSEQ + l0 + t)*64 + d] = softplusf(x);
    }
}

// ======== global front: GEMM + LN + dwconv + silu + FUSED proj/delta ========
__global__ void __launch_bounds__(128) k_global_front(
    const float* __restrict__ f1, const float* __restrict__ f2,
    const float* __restrict__ Wg, const float* __restrict__ bg,
    const float* __restrict__ ln_g, const float* __restrict__ ln_b,
    const float* __restrict__ wcg, const float* __restrict__ bcg,
    const float* __restrict__ Wxp, const float* __restrict__ Wdt,
    const float* __restrict__ bdt)
{
    const int TF = 32;
    __shared__ __align__(16) float sh[TF+3][132];
    __shared__ __align__(16) float sbuf[36*132];  // sx[35][64] @0, tmp[64][35] @2496; later swx[36][132]
    __shared__ float sdt[TF][4];
    float (*sx)[64]   = (float(*)[64])sbuf;
    float (*swx)[132] = (float(*)[132])sbuf;
    int s = blockIdx.x;
    const float* f = ((s >> 1) ? f2 : f1) + (size_t)(s & 1) * 64 * LSEQ;
    int l0 = blockIdx.y * TF;
    int tid = threadIdx.x, lane = tid & 31, wid = tid >> 5;

    // coalesced load + transpose
    {
        float (*tmp)[TF+3] = (float(*)[TF+3])(sbuf + 2496);   // 64 x 35
        for (int r = wid; r < 64; r += 4) {
            const float* fr = f + (size_t)r*LSEQ + l0 - 1;
            #pragma unroll
            for (int j = lane; j < TF+3; j += 32) {
                int gl = l0 - 1 + j;
                tmp[r][j] = (gl >= 0 && gl < LSEQ) ? fr[j] : 0.f;
            }
        }
        __syncthreads();
        for (int j = wid; j < TF+3; j += 4) {
            sx[j][lane]      = tmp[lane][j];
            sx[j][lane + 32] = tmp[lane + 32][j];
        }
    }
    __syncthreads();

    int c = tid;
    {
        float w[64];
        #pragma unroll 16
        for (int k = 0; k < 64; k++) w[k] = Wg[c*64 + k];
        float bias = bg[c];
        for (int j = 0; j < TF+3; j++)
            sh[j][c] = bias + dot64((const float4*)sx[j], w);
    }
    __syncthreads();

    // sx/tmp dead: load swx into sbuf
    for (int i = tid; i < 36*128; i += 128) swx[i >> 7][i & 127] = Wxp[i];

    {
        float g0 = ln_g[lane],    g1 = ln_g[lane+32], g2 = ln_g[lane+64], g3 = ln_g[lane+96];
        float b0 = ln_b[lane],    b1 = ln_b[lane+32], b2 = ln_b[lane+64], b3 = ln_b[lane+96];
        for (int t = wid; t < TF+3; t += 4) {
            float a0 = sh[t][lane], a1 = sh[t][lane+32], a2 = sh[t][lane+64], a3 = sh[t][lane+96];
            float s1 = a0+a1+a2+a3;
            float s2 = a0*a0+a1*a1+a2*a2+a3*a3;
            #pragma unroll
            for (int o = 16; o; o >>= 1) {
                s1 += __shfl_xor_sync(0xffffffffu, s1, o);
                s2 += __shfl_xor_sync(0xffffffffu, s2, o);
            }
            float mu = s1 * (1.f/128.f);
            float rs = rsqrtf(s2 * (1.f/128.f) - mu*mu + 1e-5f);
            sh[t][lane]    = (a0-mu)*rs*g0 + b0;
            sh[t][lane+32] = (a1-mu)*rs*g1 + b1;
            sh[t][lane+64] = (a2-mu)*rs*g2 + b2;
            sh[t][lane+96] = (a3-mu)*rs*g3 + b3;
        }
    }
    __syncthreads();

    {
        float cw0 = wcg[c*4], cw1 = wcg[c*4+1], cw2 = wcg[c*4+2], cw3 = wcg[c*4+3];
        float cb = bcg[c];
        float* outp = g_Ug + (size_t)s*LSEQ*128 + c;
        float x0 = 0.f, x1 = 0.f, x2 = 0.f;
        for (int j = 0; j < TF+3; j++) {
            int gl = l0 - 1 + j;
            float xn = (gl >= 0 && gl < LSEQ) ? sh[j][c] : 0.f;
            if (j >= 3) {
                float y = cw0*x0 + cw1*x1 + cw2*x2 + cw3*xn + cb;
                float v = siluf(y);
                outp[(size_t)(l0 + j - 3) * 128] = v;
                sh[j-3][c] = v;
            }
            x0 = x1; x1 = x2; x2 = xn;
        }
    }
    __syncthreads();

    {
        int t = tid >> 2, q = tid & 3;
        float accr[9];
        #pragma unroll
        for (int j = 0; j < 9; j++) accr[j] = 0.f;
        const float4* u4 = (const float4*)sh[t];
        #pragma unroll
        for (int k4 = 0; k4 < 32; k4++) {
            float4 uv = u4[k4];
            #pragma unroll
            for (int j = 0; j < 9; j++) {
                float4 wv = ((const float4*)swx[q*9 + j])[k4];
                accr[j] += uv.x*wv.x + uv.y*wv.y + uv.z*wv.z + uv.w*wv.w;
            }
        }
        #pragma unroll
        for (int j = 0; j < 9; j++) {
            int r = q*9 + j;
            if (r < 4) sdt[t][r] = accr[j];
            else g_BCg[((size_t)s*LSEQ + l0 + t)*32 + (r-4)] = accr[j];
        }
    }
    __syncthreads();

    for (int i = tid; i < TF*128; i += 128) {
        int t = i >> 7, d = i & 127;
        float x = sdt[t][0]*Wdt[d*4]   + sdt[t][1]*Wdt[d*4+1]
                + sdt[t][2]*Wdt[d*4+2] + sdt[t][3]*Wdt[d*4+3] + bdt[d];
        g_dg[((size_t)s*LSEQ + l0 + t)*128 + d] = softplusf(x);
    }
}

// -------------------- shared staging for scan kernels -----------------------
template<int D, int NT>
__device__ __forceinline__ void stage_tile(
    const float* __restrict__ DEL, const float* __restrict__ U,
    const float* __restrict__ BC, size_t base, int tid,
    float* s_del, float* s_u, float* s_bc)
{
    const float4* gdel = (const float4*)(DEL + base*D);
    const float4* gu   = (const float4*)(U   + base*D);
    const float4* gbc  = (const float4*)(BC  + base*32);
    float4* sdel = (float4*)s_del;
    float4* su4  = (float4*)s_u;
    float4* sbc  = (float4*)s_bc;
    #pragma unroll
    for (int i = 0; i < NT*D/4/128; i++) { int k = i*128 + tid; sdel[k] = gdel[k]; }
    #pragma unroll
    for (int i = 0; i < NT*D/4/128; i++) { int k = i*128 + tid; su4[k]  = gu[k]; }
    #pragma unroll
    for (int k = tid; k < NT*8; k += 128) sbc[k] = gbc[k];
}

// ---------------- scan phase A body ------------------------------------------
template<int D>
__device__ __forceinline__ void scanA_body(
    const float* __restrict__ Alog, float* __restrict__ Sum,
    const float* s_del, const float* s_u, const float* s_bc,
    size_t chunkIdx, int d, int off)
{
    float Ar[16];
    bool st = loadA(Alog, d, Ar);
    float A0 = Ar[0];
    float h[16];
    #pragma unroll
    for (int n = 0; n < 16; n++) h[n] = 0.f;
    float S = 0.f;
    const float4* bc = (const float4*)s_bc;
    #pragma unroll 4
    for (int t = 0; t < TCH; t++) {
        int tt = off + t;
        float del = s_del[tt*D + d];
        float du  = del * s_u[tt*D + d];
        float4 b0 = bc[tt*8+0], b1 = bc[tt*8+1], b2 = bc[tt*8+2], b3 = bc[tt*8+3];
        float a[16];
        if (st) powers16(__expf(del*A0), a);
        else {
            #pragma unroll
            for (int n = 0; n < 16; n++) a[n] = __expf(del*Ar[n]);
        }
        h[0]=a[0]*h[0]+du*b0.x;  h[1]=a[1]*h[1]+du*b0.y;
        h[2]=a[2]*h[2]+du*b0.z;  h[3]=a[3]*h[3]+du*b0.w;
        h[4]=a[4]*h[4]+du*b1.x;  h[5]=a[5]*h[5]+du*b1.y;
        h[6]=a[6]*h[6]+du*b1.z;  h[7]=a[7]*h[7]+du*b1.w;
        h[8]=a[8]*h[8]+du*b2.x;  h[9]=a[9]*h[9]+du*b2.y;
        h[10]=a[10]*h[10]+du*b2.z; h[11]=a[11]*h[11]+du*b2.w;
        h[12]=a[12]*h[12]+du*b3.x; h[13]=a[13]*h[13]+du*b3.y;
        h[14]=a[14]*h[14]+du*b3.z; h[15]=a[15]*h[15]+du*b3.w;
        S += del;
    }
    float ap[16];
    if (st) powers16(__expf(S*A0), ap);
    else {
        #pragma unroll
        for (int n = 0; n < 16; n++) ap[n] = __expf(S*Ar[n]);
    }
    float4* o = (float4*)(Sum + (chunkIdx*D + d)*32);
    float4* hv = (float4*)h;
    float4* av = (float4*)ap;
    #pragma unroll
    for (int n = 0; n < 4; n++) { o[n] = hv[n]; o[4+n] = av[n]; }
}

__global__ void __launch_bounds__(128) k_scanA_m(const float* __restrict__ Alog_m)
{
    __shared__ __align__(16) float s_del[2*TCH*64];
    __shared__ __align__(16) float s_u  [2*TCH*64];
    __shared__ __align__(16) float s_bc [2*TCH*32];
    int tid = threadIdx.x;
    int bid = blockIdx.x;
    int s = bid / (NCHK/2), cp = bid - s*(NCHK/2);
    size_t base = (size_t)s*LSEQ + (size_t)cp*(2*TCH);
    stage_tile<64,2*TCH>(g_dm, g_Um, g_BCm, base, tid, s_del, s_u, s_bc);
    __syncthreads();
    int half = tid >> 6, d = tid & 63;
    scanA_body<64>(Alog_m, g_SumM, s_del, s_u, s_bc,
                   (size_t)s*NCHK + cp*2 + half, d, half*TCH);
}

__global__ void __launch_bounds__(128) k_scanA_g(const float* __restrict__ Alog_g)
{
    __shared__ __align__(16) float s_del[TCH*128];
    __shared__ __align__(16) float s_u  [TCH*128];
    __shared__ __align__(16) float s_bc [TCH*32];
    int tid = threadIdx.x;
    int bid = blockIdx.x;
    int s = bid / NCHK, ch = bid - s*NCHK;
    size_t base = (size_t)s*LSEQ + (size_t)ch*TCH;
    stage_tile<128,TCH>(g_dg, g_Ug, g_BCg, base, tid, s_del, s_u, s_bc);
    __syncthreads();
    scanA_body<128>(Alog_g, g_SumG, s_del, s_u, s_bc,
                    (size_t)s*NCHK + ch, tid, 0);
}

// ============ scan phase B: hierarchical prefix (no aliasing) ===============
template<int D>
__device__ __forceinline__ void scanB1_body(int t)
{
    const float* Sum = (D == 64) ? g_SumM : g_SumG;
    float* GA = (D == 64) ? g_GAm : g_GAg;
    float* GB = (D == 64) ? g_GBm : g_GBg;
    int n = t & 15;
    int g = (t >> 4) % NGRP;
    int rest = t / (16*NGRP);
    int d = rest % D, s = rest / D;
    const float* p = Sum + (((size_t)s*NCHK + g*GSZ)*D + d)*32 + n;
    float A = 1.f, B = 0.f;
    #pragma unroll 4
    for (int c = 0; c < GSZ; c++) {
        float b = p[(size_t)c*D*32];
        float a = p[(size_t)c*D*32 + 16];
        A = a*A; B = a*B + b;
    }
    size_t gi = (((size_t)s*NGRP + g)*D + d)*16 + n;
    GA[gi] = A; GB[gi] = B;
}
__global__ void __launch_bounds__(256) k_scanB1_m()
{
    int t = blockIdx.x * 256 + threadIdx.x;
    if (t < 4*64*16*NGRP) scanB1_body<64>(t);
}
__global__ void __launch_bounds__(256) k_scanB1_g()
{
    int t = blockIdx.x * 256 + threadIdx.x;
    if (t < 4*128*16*NGRP) scanB1_body<128>(t);
}
template<int D>
__device__ __forceinline__ void scanB2_body(int t)
{
    const float* GA = (D == 64) ? g_GAm : g_GAg;
    const float* GB = (D == 64) ? g_GBm : g_GBg;
    float* GH = (D == 64) ? g_GHm : g_GHg;
    int n = t & 15;
    int d = (t >> 4) % D;
    int s = t / (D*16);
    size_t stride = (size_t)D*16;
    size_t base = ((size_t)s*NGRP*D + d)*16 + n;
    float P = 0.f;
    #pragma unroll 3
    for (int g = 0; g < NGRP; g++) {
        size_t gi = base + (size_t)g*stride;
        GH[gi] = P;
        P = GA[gi]*P + GB[gi];
    }
}
__global__ void __launch_bounds__(256) k_scanB2()
{
    int t = blockIdx.x * 256 + threadIdx.x;
    const int NM = 4*64*16;
    if (t < NM) scanB2_body<64>(t);
    else {
        t -= NM;
        if (t < 4*128*16) scanB2_body<128>(t);
    }
}
template<int D>
__device__ __forceinline__ void scanB3_body(int t)
{
    const float* Sum = (D == 64) ? g_SumM : g_SumG;
    const float* GH  = (D == 64) ? g_GHm : g_GHg;
    float* Hin = (D == 64) ? g_HinM : g_HinG;
    int n = t & 15;
    int g = (t >> 4) % NGRP;
    int rest = t / (16*NGRP);
    int d = rest % D, s = rest / D;
    float hin = GH[(((size_t)s*NGRP + g)*D + d)*16 + n];
    const float* p = Sum + (((size_t)s*NCHK + g*GSZ)*D + d)*32 + n;
    float* hp = Hin + (((size_t)s*NCHK + g*GSZ)*D + d)*16 + n;
    #pragma unroll 4
    for (int c = 0; c < GSZ; c++) {
        hp[(size_t)c*D*16] = hin;
        float b = p[(size_t)c*D*32];
        float a = p[(size_t)c*D*32 + 16];
        hin = a*hin + b;
    }
}
__global__ void __launch_bounds__(256) k_scanB3()
{
    int t = blockIdx.x * 256 + threadIdx.x;
    const int NM = 4*64*16*NGRP;
    if (t < NM) scanB3_body<64>(t);
    else {
        t -= NM;
        if (t < 4*128*16*NGRP) scanB3_body<128>(t);
    }
}

// ---------------- scan phase C body + merged kernel --------------------------
template<int D>
__device__ __forceinline__ void scanC_body(
    const float* __restrict__ Alog, const float* __restrict__ Dp,
    const float* __restrict__ Hin, float* __restrict__ Y,
    const float* s_del, const float* s_u, const float* s_bc,
    size_t chunkIdx, int d, int off, size_t base)
{
    float Ar[16];
    bool st = loadA(Alog, d, Ar);
    float A0 = Ar[0];
    float h[16];
    const float4* hp = (const float4*)(Hin + (chunkIdx*D + d)*16);
    float4 h0 = hp[0], h1 = hp[1], h2 = hp[2], h3 = hp[3];
    h[0]=h0.x; h[1]=h0.y; h[2]=h0.z; h[3]=h0.w;
    h[4]=h1.x; h[5]=h1.y; h[6]=h1.z; h[7]=h1.w;
    h[8]=h2.x; h[9]=h2.y; h[10]=h2.z; h[11]=h2.w;
    h[12]=h3.x; h[13]=h3.y; h[14]=h3.z; h[15]=h3.w;
    float Dd = Dp[d];
    const float4* bc = (const float4*)s_bc;
    float* yp = Y + (base + off)*D + d;
    #pragma unroll 4
    for (int t = 0; t < TCH; t++) {
        int tt = off + t;
        float del = s_del[tt*D + d];
        float u   = s_u  [tt*D + d];
        float du  = del * u;
        float4 b0 = bc[tt*8+0], b1 = bc[tt*8+1], b2 = bc[tt*8+2], b3 = bc[tt*8+3];
        float4 c0 = bc[tt*8+4], c1 = bc[tt*8+5], c2 = bc[tt*8+6], c3 = bc[tt*8+7];
        float a[16];
        if (st) powers16(__expf(del*A0), a);
        else {
            #pragma unroll
            for (int n = 0; n < 16; n++) a[n] = __expf(del*Ar[n]);
        }
        h[0]=a[0]*h[0]+du*b0.x;  h[1]=a[1]*h[1]+du*b0.y;
        h[2]=a[2]*h[2]+du*b0.z;  h[3]=a[3]*h[3]+du*b0.w;
        h[4]=a[4]*h[4]+du*b1.x;  h[5]=a[5]*h[5]+du*b1.y;
        h[6]=a[6]*h[6]+du*b1.z;  h[7]=a[7]*h[7]+du*b1.w;
        h[8]=a[8]*h[8]+du*b2.x;  h[9]=a[9]*h[9]+du*b2.y;
        h[10]=a[10]*h[10]+du*b2.z; h[11]=a[11]*h[11]+du*b2.w;
        h[12]=a[12]*h[12]+du*b3.x; h[13]=a[13]*h[13]+du*b3.y;
        h[14]=a[14]*h[14]+du*b3.z; h[15]=a[15]*h[15]+du*b3.w;
        float y = Dd*u;
        y += h[0]*c0.x + h[1]*c0.y + h[2]*c0.z + h[3]*c0.w;
        y += h[4]*c1.x + h[5]*c1.y + h[6]*c1.z + h[7]*c1.w;
        y += h[8]*c2.x + h[9]*c2.y + h[10]*c2.z + h[11]*c2.w;
        y += h[12]*c3.x + h[13]*c3.y + h[14]*c3.z + h[15]*c3.w;
        yp[(size_t)t*D] = y;
    }
}

__global__ void __launch_bounds__(128) k_scanC_all(
    const float* __restrict__ Alog_m, const float* __restrict__ Dm,
    const float* __restrict__ Alog_g, const float* __restrict__ Dg)
{
    __shared__ __align__(16) float s_del[2*TCH*64];
    __shared__ __align__(16) float s_u  [2*TCH*64];
    __shared__ __align__(16) float s_bc [2*TCH*32];
    int tid = threadIdx.x;
    int bid = blockIdx.x;
    if (bid < 4*NCHK) {
        int s = bid / NCHK, ch = bid - s*NCHK;
        size_t base = (size_t)s*LSEQ + (size_t)ch*TCH;
        stage_tile<128,TCH>(g_dg, g_Ug, g_BCg, base, tid, s_del, s_u, s_bc);
        __syncthreads();
        scanC_body<128>(Alog_g, Dg, g_HinG, g_yg, s_del, s_u, s_bc,
                        (size_t)s*NCHK + ch, tid, 0, base);
    } else {
        bid -= 4*NCHK;
        int s = bid / (NCHK/2), cp = bid - s*(NCHK/2);
        size_t base = (size_t)s*LSEQ + (size_t)cp*(2*TCH);
        stage_tile<64,2*TCH>(g_dm, g_Um, g_BCm, base, tid, s_del, s_u, s_bc);
        __syncthreads();
        int half = tid >> 6, d = tid & 63;
        scanC_body<64>(Alog_m, Dm, g_HinM, g_ym, s_del, s_u, s_bc,
                       (size_t)s*NCHK + cp*2 + half, d, half*TCH, base);
    }
}

// ---------------- output: o = (mixer ⊙ global) @ Wo^T + bo -------------------
__global__ void __launch_bounds__(256) k_out(
    const float* __restrict__ Wo, const float* __restrict__ bo,
    float* __restrict__ out)
{
    __shared__ __align__(16) float sp[64*132];
    int o = blockIdx.y >> 1, b = blockIdx.y & 1;
    int l0 = blockIdx.x * 64;
    int tid = threadIdx.x;

    int sm = (o == 0) ? b : 2 + b;
    int sg = (o == 0) ? 2 + b : b;
    const float* ym = g_ym + ((size_t)sm*LSEQ + l0)*64;
    const float* zz = g_Z  + ((size_t)sm*LSEQ + l0)*64;
    const float* yg = g_yg + ((size_t)sg*LSEQ + l0)*128;

    for (int i = tid; i < 64*128; i += 256) {
        int t = i >> 7, k = i & 127;
        float m = (k < 64) ? ym[t*64 + k] : zz[t*64 + (k-64)];
        sp[t*132 + k] = m * yg[t*128 + k];
    }
    __syncthreads();

    int tx = tid & 15, ty = tid >> 4;
    int ch0 = tx * 4, t0 = ty * 4;
    float acc[4][4];
    #pragma unroll
    for (int i = 0; i < 4; i++)
        #pragma unroll
        for (int j = 0; j < 4; j++) acc[i][j] = 0.f;

    const float4* p0 = (const float4*)(sp + (t0+0)*132);
    const float4* p1 = (const float4*)(sp + (t0+1)*132);
    const float4* p2 = (const float4*)(sp + (t0+2)*132);
    const float4* p3 = (const float4*)(sp + (t0+3)*132);
    const float4* w0 = (const float4*)(Wo + (ch0+0)*128);
    const float4* w1 = (const float4*)(Wo + (ch0+1)*128);
    const float4* w2 = (const float4*)(Wo + (ch0+2)*128);
    const float4* w3 = (const float4*)(Wo + (ch0+3)*128);
    #pragma unroll 8
    for (int k4 = 0; k4 < 32; k4++) {
        float4 pv[4] = { p0[k4], p1[k4], p2[k4], p3[k4] };
        float4 wv[4] = { __ldg(w0+k4), __ldg(w1+k4), __ldg(w2+k4), __ldg(w3+k4) };
        #pragma unroll
        for (int i = 0; i < 4; i++)
            #pragma unroll
            for (int j = 0; j < 4; j++)
                acc[i][j] += pv[i].x*wv[j].x + pv[i].y*wv[j].y
                           + pv[i].z*wv[j].z + pv[i].w*wv[j].w;
    }
    float* op = out + ((size_t)o*2 + b)*64*LSEQ;
    #pragma unroll
    for (int j = 0; j < 4; j++) {
        float bj = bo[ch0 + j];
        float4 v = { acc[0][j]+bj, acc[1][j]+bj, acc[2][j]+bj, acc[3][j]+bj };
        *(float4*)(op + (size_t)(ch0+j)*LSEQ + l0 + t0) = v;
    }
}

// -----------------------------------------------------------------------------
extern "C" void kernel_launch(void* const* d_in, const int* in_sizes, int n_in,
                              void* d_out, int out_size)
{
    const float* f1    = (const float*)d_in[0];
    const float* f2    = (const float*)d_in[1];
    const float* Wi    = (const float*)d_in[2];
    const float* bi    = (const float*)d_in[3];
    const float* wcx   = (const float*)d_in[4];
    const float* bcx   = (const float*)d_in[5];
    const float* wcz   = (const float*)d_in[6];
    const float* bcz   = (const float*)d_in[7];
    const float* Wxp_m = (const float*)d_in[8];
    const float* Wdt_m = (const float*)d_in[9];
    const float* bdt_m = (const float*)d_in[10];
    const float* Alog_m= (const float*)d_in[11];
    const float* Dm    = (const float*)d_in[12];
    const float* Wg    = (const float*)d_in[13];
    const float* bg    = (const float*)d_in[14];
    const float* ln_g  = (const float*)d_in[15];
    const float* ln_b  = (const float*)d_in[16];
    const float* wcg   = (const float*)d_in[17];
    const float* bcg   = (const float*)d_in[18];
    const float* Wxp_g = (const float*)d_in[19];
    const float* Wdt_g = (const float*)d_in[20];
    const float* bdt_g = (const float*)d_in[21];
    const float* Alog_g= (const float*)d_in[22];
    const float* Dg    = (const float*)d_in[23];
    const float* Wo    = (const float*)d_in[24];
    const float* bo    = (const float*)d_in[25];
    float* out = (float*)d_out;

    // launch order chosen so the profiled launch (index 3) is k_global_front
    k_mixer_front <<<dim3(4, LSEQ/64), 128>>>(f1, f2, Wi, bi, wcx, bcx, wcz, bcz,
                                              Wxp_m, Wdt_m, bdt_m);          // 0
    k_scanA_m    <<<4*(NCHK/2), 128>>>(Alog_m);                              // 1
    k_scanB1_m   <<<(4*64*16*NGRP + 255)/256, 256>>>();                      // 2
    k_global_front<<<dim3(4, LSEQ/32), 128>>>(f1, f2, Wg, bg, ln_g, ln_b,
                                              wcg, bcg, Wxp_g, Wdt_g, bdt_g);// 3 <- profiled
    k_scanA_g    <<<4*NCHK, 128>>>(Alog_g);                                  // 4
    k_scanB1_g   <<<(4*128*16*NGRP + 255)/256, 256>>>();                     // 5
    k_scanB2     <<<(4*64*16 + 4*128*16 + 255)/256, 256>>>();                // 6
    k_scanB3     <<<(4*64*16*NGRP + 4*128*16*NGRP + 255)/256, 256>>>();      // 7
    k_scanC_all  <<<4*NCHK + 4*(NCHK/2), 128>>>(Alog_m, Dm, Alog_g, Dg);     // 8
    k_out        <<<dim3(LSEQ/64, 4), 256>>>(Wo, bo, out);                   // 9
}

// round 15
// speedup vs baseline: 1.1354x; 1.1354x over previous
#include <cuda_runtime.h>
#include <math.h>

#define LSEQ 9216
#define NCHK 288
#define TCH  32
#define NGRP 18
#define GSZ  16

typedef unsigned long long u64;

// ------------------------- scratch (device globals) -------------------------
__device__ __align__(16) float g_Um [4*LSEQ*64];
__device__ __align__(16) float g_Z  [4*LSEQ*64];
__device__ __align__(16) float g_dm [4*LSEQ*64];
__device__ __align__(16) float g_BCm[4*LSEQ*32];
__device__ __align__(16) float g_ym [4*LSEQ*64];
__device__ __align__(16) float g_Ug [4*LSEQ*128];
__device__ __align__(16) float g_dg [4*LSEQ*128];
__device__ __align__(16) float g_BCg[4*LSEQ*32];
__device__ __align__(16) float g_yg [4*LSEQ*128];
__device__ __align__(16) float g_SumM[4*NCHK*64*32];
__device__ __align__(16) float g_SumG[(size_t)4*NCHK*128*32];
__device__ __align__(16) float g_HinM[4*NCHK*64*16];
__device__ __align__(16) float g_HinG[4*NCHK*128*16];
__device__ __align__(16) float g_GAm[4*NGRP*64*16];
__device__ __align__(16) float g_GBm[4*NGRP*64*16];
__device__ __align__(16) float g_GHm[4*NGRP*64*16];
__device__ __align__(16) float g_GAg[4*NGRP*128*16];
__device__ __align__(16) float g_GBg[4*NGRP*128*16];
__device__ __align__(16) float g_GHg[4*NGRP*128*16];

__device__ __forceinline__ float siluf(float y) {
    return y / (1.f + __expf(-y));
}
__device__ __forceinline__ float softplusf(float x) {
    return (x > 20.f) ? x : log1pf(expf(x));
}
// ---- packed f32x2 helpers (sm_100+ PTX) ----
__device__ __forceinline__ void fma2(u64& d, u64 a, u64 b) {
    asm("fma.rn.f32x2 %0, %1, %2, %0;" : "+l"(d) : "l"(a), "l"(b));
}
__device__ __forceinline__ float upksum(u64 v) {
    float lo, hi;
    asm("mov.b64 {%0,%1}, %2;" : "=f"(lo), "=f"(hi) : "l"(v));
    return lo + hi;
}
// packed dot of 64 floats: row (smem, 16B aligned), w2[32] packed weights
__device__ __forceinline__ float dot64p(const float* rowf, const u64* w2) {
    const ulonglong2* row = (const ulonglong2*)rowf;
    u64 a0 = 0ull, a1 = 0ull, a2 = 0ull, a3 = 0ull;
    #pragma unroll
    for (int k = 0; k < 16; k += 4) {
        ulonglong2 r0 = row[k],   r1 = row[k+1];
        ulonglong2 r2 = row[k+2], r3 = row[k+3];
        fma2(a0, r0.x, w2[2*k+0]); fma2(a1, r0.y, w2[2*k+1]);
        fma2(a2, r1.x, w2[2*k+2]); fma2(a3, r1.y, w2[2*k+3]);
        fma2(a0, r2.x, w2[2*k+4]); fma2(a1, r2.y, w2[2*k+5]);
        fma2(a2, r3.x, w2[2*k+6]); fma2(a3, r3.y, w2[2*k+7]);
    }
    return (upksum(a0) + upksum(a1)) + (upksum(a2) + upksum(a3));
}
// pw[k] = e1^(k+1)
__device__ __forceinline__ void powers16(float e1, float* pw) {
    pw[0]=e1;
    pw[1]=pw[0]*pw[0];  pw[2]=pw[1]*pw[0];  pw[3]=pw[1]*pw[1];
    pw[4]=pw[2]*pw[1];  pw[5]=pw[2]*pw[2];  pw[6]=pw[3]*pw[2];  pw[7]=pw[3]*pw[3];
    pw[8]=pw[4]*pw[3];  pw[9]=pw[4]*pw[4];  pw[10]=pw[5]*pw[4]; pw[11]=pw[5]*pw[5];
    pw[12]=pw[6]*pw[5]; pw[13]=pw[6]*pw[6]; pw[14]=pw[7]*pw[6]; pw[15]=pw[7]*pw[7];
}
__device__ __forceinline__ bool loadA(const float* Alog, int d, float* Ar) {
    #pragma unroll
    for (int n = 0; n < 16; n++) Ar[n] = -__expf(Alog[d*16 + n]);
    bool st = true;
    #pragma unroll
    for (int n = 1; n < 16; n++)
        if (fabsf(Ar[n] - (float)(n+1)*Ar[0]) > 1e-4f * fabsf(Ar[n])) st = false;
    return st;
}

// ======== mixer front: GEMM + dwconv + silu + FUSED proj/delta ==============
__global__ void __launch_bounds__(128) k_mixer_front(
    const float* __restrict__ f1, const float* __restrict__ f2,
    const float* __restrict__ Wi, const float* __restrict__ bi,
    const float* __restrict__ wcx, const float* __restrict__ bcx,
    const float* __restrict__ wcz, const float* __restrict__ bcz,
    const float* __restrict__ Wxp, const float* __restrict__ Wdt,
    const float* __restrict__ bdt)
{
    const int TF = 64;
    __shared__ __align__(16) float sx[TF+3][64];
    __shared__ __align__(16) float su[TF][68];    // also tmp[64][67] staging
    __shared__ __align__(16) float swx[36][68];
    __shared__ float sdt[TF][4];
    int s = blockIdx.x;
    const float* f = ((s >> 1) ? f2 : f1) + (size_t)(s & 1) * 64 * LSEQ;
    int l0 = blockIdx.y * TF;
    int tid = threadIdx.x, lane = tid & 31, w4 = tid >> 5;

    {   // coalesced load: warp per channel row, lanes along sequence
        float (*tmp)[TF+3] = (float(*)[TF+3])su;
        for (int r = w4; r < 64; r += 4) {
            const float* fr = f + (size_t)r*LSEQ + l0 - 1;
            #pragma unroll
            for (int j = lane; j < TF+3; j += 32) {
                int gl = l0 - 1 + j;
                tmp[r][j] = (gl >= 0 && gl < LSEQ) ? fr[j] : 0.f;
            }
        }
        for (int i = tid; i < 36*64; i += 128) swx[i >> 6][i & 63] = Wxp[i];
        __syncthreads();
        for (int j = w4; j < TF+3; j += 4) {
            sx[j][lane]      = tmp[lane][j];
            sx[j][lane + 32] = tmp[lane + 32][j];
        }
    }
    __syncthreads();

    int c = tid;
    {
        u64 w2[32];
        const ulonglong2* wrow = (const ulonglong2*)(Wi + c*64);
        #pragma unroll
        for (int i = 0; i < 16; i++) { ulonglong2 t = wrow[i]; w2[2*i] = t.x; w2[2*i+1] = t.y; }
        float bias = bi[c];
        const float* cw = (c < 64) ? (wcx + c*4) : (wcz + (c-64)*4);
        float cw0 = cw[0], cw1 = cw[1], cw2 = cw[2], cw3 = cw[3];
        float cb = (c < 64) ? bcx[c] : bcz[c-64];
        bool isx = (c < 64);
        float* outp = isx ? (g_Um + (size_t)s*LSEQ*64 + c)
                          : (g_Z  + (size_t)s*LSEQ*64 + (c-64));
        float x0 = 0.f, x1 = 0.f, x2 = 0.f;
        for (int j = 0; j < TF+3; j++) {
            int gl = l0 - 1 + j;
            float acc = bias + dot64p(sx[j], w2);
            if (gl < 0 || gl >= LSEQ) acc = 0.f;
            if (j >= 3) {
                float y = cw0*x0 + cw1*x1 + cw2*x2 + cw3*acc + cb;
                float v = siluf(y);
                outp[(size_t)(l0 + j - 3) * 64] = v;
                if (isx) su[j-3][c] = v;
            }
            x0 = x1; x1 = x2; x2 = acc;
        }
    }
    __syncthreads();

    // ---- fused proj (packed) ----
    {
        int q = tid & 3;
        #pragma unroll
        for (int p = 0; p < 2; p++) {
            int t = p*32 + (tid >> 2);
            u64 accp[9];
            #pragma unroll
            for (int j = 0; j < 9; j++) accp[j] = 0ull;
            const ulonglong2* u2 = (const ulonglong2*)su[t];
            #pragma unroll
            for (int k4 = 0; k4 < 16; k4++) {
                ulonglong2 uv = u2[k4];
                #pragma unroll
                for (int j = 0; j < 9; j++) {
                    ulonglong2 wv = ((const ulonglong2*)swx[q*9 + j])[k4];
                    fma2(accp[j], uv.x, wv.x);
                    fma2(accp[j], uv.y, wv.y);
                }
            }
            #pragma unroll
            for (int j = 0; j < 9; j++) {
                int r = q*9 + j;
                float v = upksum(accp[j]);
                if (r < 4) sdt[t][r] = v;
                else g_BCm[((size_t)s*LSEQ + l0 + t)*32 + (r-4)] = v;
            }
        }
    }
    __syncthreads();

    for (int i = tid; i < TF*64; i += 128) {
        int t = i >> 6, d = i & 63;
        float x = sdt[t][0]*Wdt[d*4]   + sdt[t][1]*Wdt[d*4+1]
                + sdt[t][2]*Wdt[d*4+2] + sdt[t][3]*Wdt[d*4+3] + bdt[d];
        g_dm[((size_t)s*LSEQ + l0 + t)*64 + d] = softplusf(x);
    }
}

// ======== global front: GEMM + LN + dwconv + silu + FUSED proj/delta ========
__global__ void __launch_bounds__(128) k_global_front(
    const float* __restrict__ f1, const float* __restrict__ f2,
    const float* __restrict__ Wg, const float* __restrict__ bg,
    const float* __restrict__ ln_g, const float* __restrict__ ln_b,
    const float* __restrict__ wcg, const float* __restrict__ bcg,
    const float* __restrict__ Wxp, const float* __restrict__ Wdt,
    const float* __restrict__ bdt)
{
    const int TF = 32;
    __shared__ __align__(16) float sh[TF+3][132];
    __shared__ __align__(16) float sbuf[36*132];  // sx[35][64]@0, tmp[64][35]@2496; later swx[36][132]
    __shared__ float sdt[TF][4];
    float (*sx)[64]   = (float(*)[64])sbuf;
    float (*swx)[132] = (float(*)[132])sbuf;
    int s = blockIdx.x;
    const float* f = ((s >> 1) ? f2 : f1) + (size_t)(s & 1) * 64 * LSEQ;
    int l0 = blockIdx.y * TF;
    int tid = threadIdx.x, lane = tid & 31, wid = tid >> 5;

    {
        float (*tmp)[TF+3] = (float(*)[TF+3])(sbuf + 2496);
        for (int r = wid; r < 64; r += 4) {
            const float* fr = f + (size_t)r*LSEQ + l0 - 1;
            #pragma unroll
            for (int j = lane; j < TF+3; j += 32) {
                int gl = l0 - 1 + j;
                tmp[r][j] = (gl >= 0 && gl < LSEQ) ? fr[j] : 0.f;
            }
        }
        __syncthreads();
        for (int j = wid; j < TF+3; j += 4) {
            sx[j][lane]      = tmp[lane][j];
            sx[j][lane + 32] = tmp[lane + 32][j];
        }
    }
    __syncthreads();

    int c = tid;
    {
        u64 w2[32];
        const ulonglong2* wrow = (const ulonglong2*)(Wg + c*64);
        #pragma unroll
        for (int i = 0; i < 16; i++) { ulonglong2 t = wrow[i]; w2[2*i] = t.x; w2[2*i+1] = t.y; }
        float bias = bg[c];
        for (int j = 0; j < TF+3; j++)
            sh[j][c] = bias + dot64p(sx[j], w2);
    }
    __syncthreads();

    for (int i = tid; i < 36*128; i += 128) swx[i >> 7][i & 127] = Wxp[i];

    {
        float g0 = ln_g[lane],    g1 = ln_g[lane+32], g2 = ln_g[lane+64], g3 = ln_g[lane+96];
        float b0 = ln_b[lane],    b1 = ln_b[lane+32], b2 = ln_b[lane+64], b3 = ln_b[lane+96];
        for (int t = wid; t < TF+3; t += 4) {
            float a0 = sh[t][lane], a1 = sh[t][lane+32], a2 = sh[t][lane+64], a3 = sh[t][lane+96];
            float s1 = a0+a1+a2+a3;
            float s2 = a0*a0+a1*a1+a2*a2+a3*a3;
            #pragma unroll
            for (int o = 16; o; o >>= 1) {
                s1 += __shfl_xor_sync(0xffffffffu, s1, o);
                s2 += __shfl_xor_sync(0xffffffffu, s2, o);
            }
            float mu = s1 * (1.f/128.f);
            float rs = rsqrtf(s2 * (1.f/128.f) - mu*mu + 1e-5f);
            sh[t][lane]    = (a0-mu)*rs*g0 + b0;
            sh[t][lane+32] = (a1-mu)*rs*g1 + b1;
            sh[t][lane+64] = (a2-mu)*rs*g2 + b2;
            sh[t][lane+96] = (a3-mu)*rs*g3 + b3;
        }
    }
    __syncthreads();

    {
        float cw0 = wcg[c*4], cw1 = wcg[c*4+1], cw2 = wcg[c*4+2], cw3 = wcg[c*4+3];
        float cb = bcg[c];
        float* outp = g_Ug + (size_t)s*LSEQ*128 + c;
        float x0 = 0.f, x1 = 0.f, x2 = 0.f;
        for (int j = 0; j < TF+3; j++) {
            int gl = l0 - 1 + j;
            float xn = (gl >= 0 && gl < LSEQ) ? sh[j][c] : 0.f;
            if (j >= 3) {
                float y = cw0*x0 + cw1*x1 + cw2*x2 + cw3*xn + cb;
                float v = siluf(y);
                outp[(size_t)(l0 + j - 3) * 128] = v;
                sh[j-3][c] = v;
            }
            x0 = x1; x1 = x2; x2 = xn;
        }
    }
    __syncthreads();

    {
        int t = tid >> 2, q = tid & 3;
        u64 accp[9];
        #pragma unroll
        for (int j = 0; j < 9; j++) accp[j] = 0ull;
        const ulonglong2* u2 = (const ulonglong2*)sh[t];
        #pragma unroll
        for (int k4 = 0; k4 < 32; k4++) {
            ulonglong2 uv = u2[k4];
            #pragma unroll
            for (int j = 0; j < 9; j++) {
                ulonglong2 wv = ((const ulonglong2*)swx[q*9 + j])[k4];
                fma2(accp[j], uv.x, wv.x);
                fma2(accp[j], uv.y, wv.y);
            }
        }
        #pragma unroll
        for (int j = 0; j < 9; j++) {
            int r = q*9 + j;
            float v = upksum(accp[j]);
            if (r < 4) sdt[t][r] = v;
            else g_BCg[((size_t)s*LSEQ + l0 + t)*32 + (r-4)] = v;
        }
    }
    __syncthreads();

    for (int i = tid; i < TF*128; i += 128) {
        int t = i >> 7, d = i & 127;
        float x = sdt[t][0]*Wdt[d*4]   + sdt[t][1]*Wdt[d*4+1]
                + sdt[t][2]*Wdt[d*4+2] + sdt[t][3]*Wdt[d*4+3] + bdt[d];
        g_dg[((size_t)s*LSEQ + l0 + t)*128 + d] = softplusf(x);
    }
}

// -------------------- shared staging for scan kernels -----------------------
template<int D, int NT>
__device__ __forceinline__ void stage_tile(
    const float* __restrict__ DEL, const float* __restrict__ U,
    const float* __restrict__ BC, size_t base, int tid,
    float* s_del, float* s_u, float* s_bc)
{
    const float4* gdel = (const float4*)(DEL + base*D);
    const float4* gu   = (const float4*)(U   + base*D);
    const float4* gbc  = (const float4*)(BC  + base*32);
    float4* sdel = (float4*)s_del;
    float4* su4  = (float4*)s_u;
    float4* sbc  = (float4*)s_bc;
    #pragma unroll
    for (int i = 0; i < NT*D/4/128; i++) { int k = i*128 + tid; sdel[k] = gdel[k]; }
    #pragma unroll
    for (int i = 0; i < NT*D/4/128; i++) { int k = i*128 + tid; su4[k]  = gu[k]; }
    #pragma unroll
    for (int k = tid; k < NT*8; k += 128) sbc[k] = gbc[k];
}

// ---------------- scan phase A body + merged kernel --------------------------
template<int D>
__device__ __forceinline__ void scanA_body(
    const float* __restrict__ Alog, float* __restrict__ Sum,
    const float* s_del, const float* s_u, const float* s_bc,
    size_t chunkIdx, int d, int off)
{
    float Ar[16];
    bool st = loadA(Alog, d, Ar);
    float A0 = Ar[0];
    float h[16];
    #pragma unroll
    for (int n = 0; n < 16; n++) h[n] = 0.f;
    float S = 0.f;
    const float4* bc = (const float4*)s_bc;
    #pragma unroll 4
    for (int t = 0; t < TCH; t++) {
        int tt = off + t;
        float del = s_del[tt*D + d];
        float du  = del * s_u[tt*D + d];
        float4 b0 = bc[tt*8+0], b1 = bc[tt*8+1], b2 = bc[tt*8+2], b3 = bc[tt*8+3];
        float a[16];
        if (st) powers16(__expf(del*A0), a);
        else {
            #pragma unroll
            for (int n = 0; n < 16; n++) a[n] = __expf(del*Ar[n]);
        }
        h[0]=a[0]*h[0]+du*b0.x;  h[1]=a[1]*h[1]+du*b0.y;
        h[2]=a[2]*h[2]+du*b0.z;  h[3]=a[3]*h[3]+du*b0.w;
        h[4]=a[4]*h[4]+du*b1.x;  h[5]=a[5]*h[5]+du*b1.y;
        h[6]=a[6]*h[6]+du*b1.z;  h[7]=a[7]*h[7]+du*b1.w;
        h[8]=a[8]*h[8]+du*b2.x;  h[9]=a[9]*h[9]+du*b2.y;
        h[10]=a[10]*h[10]+du*b2.z; h[11]=a[11]*h[11]+du*b2.w;
        h[12]=a[12]*h[12]+du*b3.x; h[13]=a[13]*h[13]+du*b3.y;
        h[14]=a[14]*h[14]+du*b3.z; h[15]=a[15]*h[15]+du*b3.w;
        S += del;
    }
    float ap[16];
    if (st) powers16(__expf(S*A0), ap);
    else {
        #pragma unroll
        for (int n = 0; n < 16; n++) ap[n] = __expf(S*Ar[n]);
    }
    float4* o = (float4*)(Sum + (chunkIdx*D + d)*32);
    float4* hv = (float4*)h;
    float4* av = (float4*)ap;
    #pragma unroll
    for (int n = 0; n < 4; n++) { o[n] = hv[n]; o[4+n] = av[n]; }
}

__global__ void __launch_bounds__(128) k_scanA_all(
    const float* __restrict__ Alog_m, const float* __restrict__ Alog_g)
{
    __shared__ __align__(16) float s_del[2*TCH*64];
    __shared__ __align__(16) float s_u  [2*TCH*64];
    __shared__ __align__(16) float s_bc [2*TCH*32];
    int tid = threadIdx.x;
    int bid = blockIdx.x;
    if (bid < 4*NCHK) {
        int s = bid / NCHK, ch = bid - s*NCHK;
        size_t base = (size_t)s*LSEQ + (size_t)ch*TCH;
        stage_tile<128,TCH>(g_dg, g_Ug, g_BCg, base, tid, s_del, s_u, s_bc);
        __syncthreads();
        scanA_body<128>(Alog_g, g_SumG, s_del, s_u, s_bc,
                        (size_t)s*NCHK + ch, tid, 0);
    } else {
        bid -= 4*NCHK;
        int s = bid / (NCHK/2), cp = bid - s*(NCHK/2);
        size_t base = (size_t)s*LSEQ + (size_t)cp*(2*TCH);
        stage_tile<64,2*TCH>(g_dm, g_Um, g_BCm, base, tid, s_del, s_u, s_bc);
        __syncthreads();
        int half = tid >> 6, d = tid & 63;
        scanA_body<64>(Alog_m, g_SumM, s_del, s_u, s_bc,
                       (size_t)s*NCHK + cp*2 + half, d, half*TCH);
    }
}

// ============ scan phase B: hierarchical prefix (no aliasing) ===============
template<int D>
__device__ __forceinline__ void scanB1_body(int t)
{
    const float* Sum = (D == 64) ? g_SumM : g_SumG;
    float* GA = (D == 64) ? g_GAm : g_GAg;
    float* GB = (D == 64) ? g_GBm : g_GBg;
    int n = t & 15;
    int g = (t >> 4) % NGRP;
    int rest = t / (16*NGRP);
    int d = rest % D, s = rest / D;
    const float* p = Sum + (((size_t)s*NCHK + g*GSZ)*D + d)*32 + n;
    float A = 1.f, B = 0.f;
    #pragma unroll 4
    for (int c = 0; c < GSZ; c++) {
        float b = p[(size_t)c*D*32];
        float a = p[(size_t)c*D*32 + 16];
        A = a*A; B = a*B + b;
    }
    size_t gi = (((size_t)s*NGRP + g)*D + d)*16 + n;
    GA[gi] = A; GB[gi] = B;
}
__global__ void __launch_bounds__(256) k_scanB1()
{
    int t = blockIdx.x * 256 + threadIdx.x;
    const int NM = 4*64*16*NGRP;
    if (t < NM) scanB1_body<64>(t);
    else {
        t -= NM;
        if (t < 4*128*16*NGRP) scanB1_body<128>(t);
    }
}
template<int D>
__device__ __forceinline__ void scanB2_body(int t)
{
    const float* GA = (D == 64) ? g_GAm : g_GAg;
    const float* GB = (D == 64) ? g_GBm : g_GBg;
    float* GH = (D == 64) ? g_GHm : g_GHg;
    int n = t & 15;
    int d = (t >> 4) % D;
    int s = t / (D*16);
    size_t stride = (size_t)D*16;
    size_t base = ((size_t)s*NGRP*D + d)*16 + n;
    float P = 0.f;
    #pragma unroll 3
    for (int g = 0; g < NGRP; g++) {
        size_t gi = base + (size_t)g*stride;
        GH[gi] = P;
        P = GA[gi]*P + GB[gi];
    }
}
__global__ void __launch_bounds__(256) k_scanB2()
{
    int t = blockIdx.x * 256 + threadIdx.x;
    const int NM = 4*64*16;
    if (t < NM) scanB2_body<64>(t);
    else {
        t -= NM;
        if (t < 4*128*16) scanB2_body<128>(t);
    }
}
template<int D>
__device__ __forceinline__ void scanB3_body(int t)
{
    const float* Sum = (D == 64) ? g_SumM : g_SumG;
    const float* GH  = (D == 64) ? g_GHm : g_GHg;
    float* Hin = (D == 64) ? g_HinM : g_HinG;
    int n = t & 15;
    int g = (t >> 4) % NGRP;
    int rest = t / (16*NGRP);
    int d = rest % D, s = rest / D;
    float hin = GH[(((size_t)s*NGRP + g)*D + d)*16 + n];
    const float* p = Sum + (((size_t)s*NCHK + g*GSZ)*D + d)*32 + n;
    float* hp = Hin + (((size_t)s*NCHK + g*GSZ)*D + d)*16 + n;
    #pragma unroll 4
    for (int c = 0; c < GSZ; c++) {
        hp[(size_t)c*D*16] = hin;
        float b = p[(size_t)c*D*32];
        float a = p[(size_t)c*D*32 + 16];
        hin = a*hin + b;
    }
}
__global__ void __launch_bounds__(256) k_scanB3()
{
    int t = blockIdx.x * 256 + threadIdx.x;
    const int NM = 4*64*16*NGRP;
    if (t < NM) scanB3_body<64>(t);
    else {
        t -= NM;
        if (t < 4*128*16*NGRP) scanB3_body<128>(t);
    }
}

// ---------------- scan phase C body + merged kernel --------------------------
template<int D>
__device__ __forceinline__ void scanC_body(
    const float* __restrict__ Alog, const float* __restrict__ Dp,
    const float* __restrict__ Hin, float* __restrict__ Y,
    const float* s_del, const float* s_u, const float* s_bc,
    size_t chunkIdx, int d, int off, size_t base)
{
    float Ar[16];
    bool st = loadA(Alog, d, Ar);
    float A0 = Ar[0];
    float h[16];
    const float4* hp = (const float4*)(Hin + (chunkIdx*D + d)*16);
    float4 h0 = hp[0], h1 = hp[1], h2 = hp[2], h3 = hp[3];
    h[0]=h0.x; h[1]=h0.y; h[2]=h0.z; h[3]=h0.w;
    h[4]=h1.x; h[5]=h1.y; h[6]=h1.z; h[7]=h1.w;
    h[8]=h2.x; h[9]=h2.y; h[10]=h2.z; h[11]=h2.w;
    h[12]=h3.x; h[13]=h3.y; h[14]=h3.z; h[15]=h3.w;
    float Dd = Dp[d];
    const float4* bc = (const float4*)s_bc;
    float* yp = Y + (base + off)*D + d;
    #pragma unroll 4
    for (int t = 0; t < TCH; t++) {
        int tt = off + t;
        float del = s_del[tt*D + d];
        float u   = s_u  [tt*D + d];
        float du  = del * u;
        float4 b0 = bc[tt*8+0], b1 = bc[tt*8+1], b2 = bc[tt*8+2], b3 = bc[tt*8+3];
        float4 c0 = bc[tt*8+4], c1 = bc[tt*8+5], c2 = bc[tt*8+6], c3 = bc[tt*8+7];
        float a[16];
        if (st) powers16(__expf(del*A0), a);
        else {
            #pragma unroll
            for (int n = 0; n < 16; n++) a[n] = __expf(del*Ar[n]);
        }
        h[0]=a[0]*h[0]+du*b0.x;  h[1]=a[1]*h[1]+du*b0.y;
        h[2]=a[2]*h[2]+du*b0.z;  h[3]=a[3]*h[3]+du*b0.w;
        h[4]=a[4]*h[4]+du*b1.x;  h[5]=a[5]*h[5]+du*b1.y;
        h[6]=a[6]*h[6]+du*b1.z;  h[7]=a[7]*h[7]+du*b1.w;
        h[8]=a[8]*h[8]+du*b2.x;  h[9]=a[9]*h[9]+du*b2.y;
        h[10]=a[10]*h[10]+du*b2.z; h[11]=a[11]*h[11]+du*b2.w;
        h[12]=a[12]*h[12]+du*b3.x; h[13]=a[13]*h[13]+du*b3.y;
        h[14]=a[14]*h[14]+du*b3.z; h[15]=a[15]*h[15]+du*b3.w;
        float y = Dd*u;
        y += h[0]*c0.x + h[1]*c0.y + h[2]*c0.z + h[3]*c0.w;
        y += h[4]*c1.x + h[5]*c1.y + h[6]*c1.z + h[7]*c1.w;
        y += h[8]*c2.x + h[9]*c2.y + h[10]*c2.z + h[11]*c2.w;
        y += h[12]*c3.x + h[13]*c3.y + h[14]*c3.z + h[15]*c3.w;
        yp[(size_t)t*D] = y;
    }
}

__global__ void __launch_bounds__(128) k_scanC_all(
    const float* __restrict__ Alog_m, const float* __restrict__ Dm,
    const float* __restrict__ Alog_g, const float* __restrict__ Dg)
{
    __shared__ __align__(16) float s_del[2*TCH*64];
    __shared__ __align__(16) float s_u  [2*TCH*64];
    __shared__ __align__(16) float s_bc [2*TCH*32];
    int tid = threadIdx.x;
    int bid = blockIdx.x;
    if (bid < 4*NCHK) {
        int s = bid / NCHK, ch = bid - s*NCHK;
        size_t base = (size_t)s*LSEQ + (size_t)ch*TCH;
        stage_tile<128,TCH>(g_dg, g_Ug, g_BCg, base, tid, s_del, s_u, s_bc);
        __syncthreads();
        scanC_body<128>(Alog_g, Dg, g_HinG, g_yg, s_del, s_u, s_bc,
                        (size_t)s*NCHK + ch, tid, 0, base);
    } else {
        bid -= 4*NCHK;
        int s = bid / (NCHK/2), cp = bid - s*(NCHK/2);
        size_t base = (size_t)s*LSEQ + (size_t)cp*(2*TCH);
        stage_tile<64,2*TCH>(g_dm, g_Um, g_BCm, base, tid, s_del, s_u, s_bc);
        __syncthreads();
        int half = tid >> 6, d = tid & 63;
        scanC_body<64>(Alog_m, Dm, g_HinM, g_ym, s_del, s_u, s_bc,
                       (size_t)s*NCHK + cp*2 + half, d, half*TCH, base);
    }
}

// ---------------- output: o = (mixer ⊙ global) @ Wo^T + bo (packed) ---------
__global__ void __launch_bounds__(256) k_out(
    const float* __restrict__ Wo, const float* __restrict__ bo,
    float* __restrict__ out)
{
    __shared__ __align__(16) float sp[64*132];
    int o = blockIdx.y >> 1, b = blockIdx.y & 1;
    int l0 = blockIdx.x * 64;
    int tid = threadIdx.x;

    int sm = (o == 0) ? b : 2 + b;
    int sg = (o == 0) ? 2 + b : b;
    const float* ym = g_ym + ((size_t)sm*LSEQ + l0)*64;
    const float* zz = g_Z  + ((size_t)sm*LSEQ + l0)*64;
    const float* yg = g_yg + ((size_t)sg*LSEQ + l0)*128;

    for (int i = tid; i < 64*128; i += 256) {
        int t = i >> 7, k = i & 127;
        float m = (k < 64) ? ym[t*64 + k] : zz[t*64 + (k-64)];
        sp[t*132 + k] = m * yg[t*128 + k];
    }
    __syncthreads();

    int tx = tid & 15, ty = tid >> 4;
    int ch0 = tx * 4, t0 = ty * 4;
    u64 acc[4][4];
    #pragma unroll
    for (int i = 0; i < 4; i++)
        #pragma unroll
        for (int j = 0; j < 4; j++) acc[i][j] = 0ull;

    const ulonglong2* p0 = (const ulonglong2*)(sp + (t0+0)*132);
    const ulonglong2* p1 = (const ulonglong2*)(sp + (t0+1)*132);
    const ulonglong2* p2 = (const ulonglong2*)(sp + (t0+2)*132);
    const ulonglong2* p3 = (const ulonglong2*)(sp + (t0+3)*132);
    const ulonglong2* w0 = (const ulonglong2*)(Wo + (ch0+0)*128);
    const ulonglong2* w1 = (const ulonglong2*)(Wo + (ch0+1)*128);
    const ulonglong2* w2 = (const ulonglong2*)(Wo + (ch0+2)*128);
    const ulonglong2* w3 = (const ulonglong2*)(Wo + (ch0+3)*128);
    #pragma unroll 8
    for (int k4 = 0; k4 < 32; k4++) {
        ulonglong2 pv[4] = { p0[k4], p1[k4], p2[k4], p3[k4] };
        ulonglong2 wv[4] = { __ldg(w0+k4), __ldg(w1+k4), __ldg(w2+k4), __ldg(w3+k4) };
        #pragma unroll
        for (int i = 0; i < 4; i++)
            #pragma unroll
            for (int j = 0; j < 4; j++) {
                fma2(acc[i][j], pv[i].x, wv[j].x);
                fma2(acc[i][j], pv[i].y, wv[j].y);
            }
    }
    float* op = out + ((size_t)o*2 + b)*64*LSEQ;
    #pragma unroll
    for (int j = 0; j < 4; j++) {
        float bj = bo[ch0 + j];
        float4 v = { upksum(acc[0][j])+bj, upksum(acc[1][j])+bj,
                     upksum(acc[2][j])+bj, upksum(acc[3][j])+bj };
        *(float4*)(op + (size_t)(ch0+j)*LSEQ + l0 + t0) = v;
    }
}

// -----------------------------------------------------------------------------
extern "C" void kernel_launch(void* const* d_in, const int* in_sizes, int n_in,
                              void* d_out, int out_size)
{
    const float* f1    = (const float*)d_in[0];
    const float* f2    = (const float*)d_in[1];
    const float* Wi    = (const float*)d_in[2];
    const float* bi    = (const float*)d_in[3];
    const float* wcx   = (const float*)d_in[4];
    const float* bcx   = (const float*)d_in[5];
    const float* wcz   = (const float*)d_in[6];
    const float* bcz   = (const float*)d_in[7];
    const float* Wxp_m = (const float*)d_in[8];
    const float* Wdt_m = (const float*)d_in[9];
    const float* bdt_m = (const float*)d_in[10];
    const float* Alog_m= (const float*)d_in[11];
    const float* Dm    = (const float*)d_in[12];
    const float* Wg    = (const float*)d_in[13];
    const float* bg    = (const float*)d_in[14];
    const float* ln_g  = (const float*)d_in[15];
    const float* ln_b  = (const float*)d_in[16];
    const float* wcg   = (const float*)d_in[17];
    const float* bcg   = (const float*)d_in[18];
    const float* Wxp_g = (const float*)d_in[19];
    const float* Wdt_g = (const float*)d_in[20];
    const float* bdt_g = (const float*)d_in[21];
    const float* Alog_g= (const float*)d_in[22];
    const float* Dg    = (const float*)d_in[23];
    const float* Wo    = (const float*)d_in[24];
    const float* bo    = (const float*)d_in[25];
    float* out = (float*)d_out;

    k_mixer_front <<<dim3(4, LSEQ/64), 128>>>(f1, f2, Wi, bi, wcx, bcx, wcz, bcz,
                                              Wxp_m, Wdt_m, bdt_m);
    k_global_front<<<dim3(4, LSEQ/32), 128>>>(f1, f2, Wg, bg, ln_g, ln_b, wcg, bcg,
                                              Wxp_g, Wdt_g, bdt_g);
    k_scanA_all  <<<4*NCHK + 4*(NCHK/2), 128>>>(Alog_m, Alog_g);
    {
        int nB1 = 4*64*16*NGRP + 4*128*16*NGRP;
        k_scanB1 <<<(nB1 + 255)/256, 256>>>();
        int nB2 = 4*64*16 + 4*128*16;
        k_scanB2 <<<(nB2 + 255)/256, 256>>>();
        k_scanB3 <<<(nB1 + 255)/256, 256>>>();
    }
    k_scanC_all  <<<4*NCHK + 4*(NCHK/2), 128>>>(Alog_m, Dm, Alog_g, Dg);
    k_out        <<<dim3(LSEQ/64, 4), 256>>>(Wo, bo, out);
}

// round 16
// speedup vs baseline: 1.1553x; 1.0175x over previous
#include <cuda_runtime.h>
#include <math.h>

#define LSEQ 9216
#define NCHK 288
#define TCH  32
#define NGRP 18
#define GSZ  16

typedef unsigned long long u64;

// ------------------------- scratch (device globals) -------------------------
__device__ __align__(16) float g_Um [4*LSEQ*64];
__device__ __align__(16) float g_Z  [4*LSEQ*64];
__device__ __align__(16) float g_dm [4*LSEQ*64];
__device__ __align__(16) float g_BCm[4*LSEQ*32];
__device__ __align__(16) float g_ym [4*LSEQ*64];
__device__ __align__(16) float g_Ug [4*LSEQ*128];
__device__ __align__(16) float g_dg [4*LSEQ*128];
__device__ __align__(16) float g_BCg[4*LSEQ*32];
__device__ __align__(16) float g_yg [4*LSEQ*128];
__device__ __align__(16) float g_SumM[4*NCHK*64*32];
__device__ __align__(16) float g_SumG[(size_t)4*NCHK*128*32];
__device__ __align__(16) float g_HinM[4*NCHK*64*16];
__device__ __align__(16) float g_HinG[4*NCHK*128*16];
__device__ __align__(16) float g_GAm[4*NGRP*64*16];
__device__ __align__(16) float g_GBm[4*NGRP*64*16];
__device__ __align__(16) float g_GHm[4*NGRP*64*16];
__device__ __align__(16) float g_GAg[4*NGRP*128*16];
__device__ __align__(16) float g_GBg[4*NGRP*128*16];
__device__ __align__(16) float g_GHg[4*NGRP*128*16];

__device__ __forceinline__ float siluf(float y) {
    return y / (1.f + __expf(-y));
}
__device__ __forceinline__ float softplusf(float x) {
    return (x > 20.f) ? x : log1pf(expf(x));
}
// ---- packed f32x2 helpers ----
__device__ __forceinline__ void fma2(u64& d, u64 a, u64 b) {
    asm("fma.rn.f32x2 %0, %1, %2, %0;" : "+l"(d) : "l"(a), "l"(b));
}
__device__ __forceinline__ float upksum(u64 v) {
    float lo, hi;
    asm("mov.b64 {%0,%1}, %2;" : "=f"(lo), "=f"(hi) : "l"(v));
    return lo + hi;
}
__device__ __forceinline__ float dot64p(const float* rowf, const u64* w2) {
    const ulonglong2* row = (const ulonglong2*)rowf;
    u64 a0 = 0ull, a1 = 0ull, a2 = 0ull, a3 = 0ull;
    #pragma unroll
    for (int k = 0; k < 16; k += 4) {
        ulonglong2 r0 = row[k],   r1 = row[k+1];
        ulonglong2 r2 = row[k+2], r3 = row[k+3];
        fma2(a0, r0.x, w2[2*k+0]); fma2(a1, r0.y, w2[2*k+1]);
        fma2(a2, r1.x, w2[2*k+2]); fma2(a3, r1.y, w2[2*k+3]);
        fma2(a0, r2.x, w2[2*k+4]); fma2(a1, r2.y, w2[2*k+5]);
        fma2(a2, r3.x, w2[2*k+6]); fma2(a3, r3.y, w2[2*k+7]);
    }
    return (upksum(a0) + upksum(a1)) + (upksum(a2) + upksum(a3));
}
__device__ __forceinline__ void powers16(float e1, float* pw) {
    pw[0]=e1;
    pw[1]=pw[0]*pw[0];  pw[2]=pw[1]*pw[0];  pw[3]=pw[1]*pw[1];
    pw[4]=pw[2]*pw[1];  pw[5]=pw[2]*pw[2];  pw[6]=pw[3]*pw[2];  pw[7]=pw[3]*pw[3];
    pw[8]=pw[4]*pw[3];  pw[9]=pw[4]*pw[4];  pw[10]=pw[5]*pw[4]; pw[11]=pw[5]*pw[5];
    pw[12]=pw[6]*pw[5]; pw[13]=pw[6]*pw[6]; pw[14]=pw[7]*pw[6]; pw[15]=pw[7]*pw[7];
}
__device__ __forceinline__ bool loadA(const float* Alog, int d, float* Ar) {
    #pragma unroll
    for (int n = 0; n < 16; n++) Ar[n] = -__expf(Alog[d*16 + n]);
    bool st = true;
    #pragma unroll
    for (int n = 1; n < 16; n++)
        if (fabsf(Ar[n] - (float)(n+1)*Ar[0]) > 1e-4f * fabsf(Ar[n])) st = false;
    return st;
}

// ======== mixer front: GEMM + dwconv + silu + FUSED proj/delta ==============
__global__ void __launch_bounds__(128) k_mixer_front(
    const float* __restrict__ f1, const float* __restrict__ f2,
    const float* __restrict__ Wi, const float* __restrict__ bi,
    const float* __restrict__ wcx, const float* __restrict__ bcx,
    const float* __restrict__ wcz, const float* __restrict__ bcz,
    const float* __restrict__ Wxp, const float* __restrict__ Wdt,
    const float* __restrict__ bdt)
{
    const int TF = 64;
    __shared__ __align__(16) float sx[TF+3][64];
    __shared__ __align__(16) float su[TF][68];
    __shared__ __align__(16) float swx[36][68];
    __shared__ float sdt[TF][4];
    int s = blockIdx.x;
    const float* f = ((s >> 1) ? f2 : f1) + (size_t)(s & 1) * 64 * LSEQ;
    int l0 = blockIdx.y * TF;
    int tid = threadIdx.x, lane = tid & 31, w4 = tid >> 5;

    {
        float (*tmp)[TF+3] = (float(*)[TF+3])su;
        for (int r = w4; r < 64; r += 4) {
            const float* fr = f + (size_t)r*LSEQ + l0 - 1;
            #pragma unroll
            for (int j = lane; j < TF+3; j += 32) {
                int gl = l0 - 1 + j;
                tmp[r][j] = (gl >= 0 && gl < LSEQ) ? fr[j] : 0.f;
            }
        }
        for (int i = tid; i < 36*64; i += 128) swx[i >> 6][i & 63] = Wxp[i];
        __syncthreads();
        for (int j = w4; j < TF+3; j += 4) {
            sx[j][lane]      = tmp[lane][j];
            sx[j][lane + 32] = tmp[lane + 32][j];
        }
    }
    __syncthreads();

    int c = tid;
    {
        u64 w2[32];
        const ulonglong2* wrow = (const ulonglong2*)(Wi + c*64);
        #pragma unroll
        for (int i = 0; i < 16; i++) { ulonglong2 t = wrow[i]; w2[2*i] = t.x; w2[2*i+1] = t.y; }
        float bias = bi[c];
        const float* cw = (c < 64) ? (wcx + c*4) : (wcz + (c-64)*4);
        float cw0 = cw[0], cw1 = cw[1], cw2 = cw[2], cw3 = cw[3];
        float cb = (c < 64) ? bcx[c] : bcz[c-64];
        bool isx = (c < 64);
        float* outp = isx ? (g_Um + (size_t)s*LSEQ*64 + c)
                          : (g_Z  + (size_t)s*LSEQ*64 + (c-64));
        float x0 = 0.f, x1 = 0.f, x2 = 0.f;
        for (int j = 0; j < TF+3; j++) {
            int gl = l0 - 1 + j;
            float acc = bias + dot64p(sx[j], w2);
            if (gl < 0 || gl >= LSEQ) acc = 0.f;
            if (j >= 3) {
                float y = cw0*x0 + cw1*x1 + cw2*x2 + cw3*acc + cb;
                float v = siluf(y);
                outp[(size_t)(l0 + j - 3) * 64] = v;
                if (isx) su[j-3][c] = v;
            }
            x0 = x1; x1 = x2; x2 = acc;
        }
    }
    __syncthreads();

    {
        int q = tid & 3;
        #pragma unroll
        for (int p = 0; p < 2; p++) {
            int t = p*32 + (tid >> 2);
            u64 accp[9];
            #pragma unroll
            for (int j = 0; j < 9; j++) accp[j] = 0ull;
            const ulonglong2* u2 = (const ulonglong2*)su[t];
            #pragma unroll
            for (int k4 = 0; k4 < 16; k4++) {
                ulonglong2 uv = u2[k4];
                #pragma unroll
                for (int j = 0; j < 9; j++) {
                    ulonglong2 wv = ((const ulonglong2*)swx[q*9 + j])[k4];
                    fma2(accp[j], uv.x, wv.x);
                    fma2(accp[j], uv.y, wv.y);
                }
            }
            #pragma unroll
            for (int j = 0; j < 9; j++) {
                int r = q*9 + j;
                float v = upksum(accp[j]);
                if (r < 4) sdt[t][r] = v;
                else g_BCm[((size_t)s*LSEQ + l0 + t)*32 + (r-4)] = v;
            }
        }
    }
    __syncthreads();

    for (int i = tid; i < TF*64; i += 128) {
        int t = i >> 6, d = i & 63;
        float x = sdt[t][0]*Wdt[d*4]   + sdt[t][1]*Wdt[d*4+1]
                + sdt[t][2]*Wdt[d*4+2] + sdt[t][3]*Wdt[d*4+3] + bdt[d];
        g_dm[((size_t)s*LSEQ + l0 + t)*64 + d] = softplusf(x);
    }
}

// ======== global front: GEMM + LN + dwconv + silu + FUSED proj/delta ========
__global__ void __launch_bounds__(128) k_global_front(
    const float* __restrict__ f1, const float* __restrict__ f2,
    const float* __restrict__ Wg, const float* __restrict__ bg,
    const float* __restrict__ ln_g, const float* __restrict__ ln_b,
    const float* __restrict__ wcg, const float* __restrict__ bcg,
    const float* __restrict__ Wxp, const float* __restrict__ Wdt,
    const float* __restrict__ bdt)
{
    const int TF = 32;
    __shared__ __align__(16) float sh[TF+3][132];
    __shared__ __align__(16) float sbuf[36*132];
    __shared__ float sdt[TF][4];
    float (*sx)[64]   = (float(*)[64])sbuf;
    float (*swx)[132] = (float(*)[132])sbuf;
    int s = blockIdx.x;
    const float* f = ((s >> 1) ? f2 : f1) + (size_t)(s & 1) * 64 * LSEQ;
    int l0 = blockIdx.y * TF;
    int tid = threadIdx.x, lane = tid & 31, wid = tid >> 5;

    {
        float (*tmp)[TF+3] = (float(*)[TF+3])(sbuf + 2496);
        for (int r = wid; r < 64; r += 4) {
            const float* fr = f + (size_t)r*LSEQ + l0 - 1;
            #pragma unroll
            for (int j = lane; j < TF+3; j += 32) {
                int gl = l0 - 1 + j;
                tmp[r][j] = (gl >= 0 && gl < LSEQ) ? fr[j] : 0.f;
            }
        }
        __syncthreads();
        for (int j = wid; j < TF+3; j += 4) {
            sx[j][lane]      = tmp[lane][j];
            sx[j][lane + 32] = tmp[lane + 32][j];
        }
    }
    __syncthreads();

    int c = tid;
    {
        u64 w2[32];
        const ulonglong2* wrow = (const ulonglong2*)(Wg + c*64);
        #pragma unroll
        for (int i = 0; i < 16; i++) { ulonglong2 t = wrow[i]; w2[2*i] = t.x; w2[2*i+1] = t.y; }
        float bias = bg[c];
        for (int j = 0; j < TF+3; j++)
            sh[j][c] = bias + dot64p(sx[j], w2);
    }
    __syncthreads();

    for (int i = tid; i < 36*128; i += 128) swx[i >> 7][i & 127] = Wxp[i];

    {
        float g0 = ln_g[lane],    g1 = ln_g[lane+32], g2 = ln_g[lane+64], g3 = ln_g[lane+96];
        float b0 = ln_b[lane],    b1 = ln_b[lane+32], b2 = ln_b[lane+64], b3 = ln_b[lane+96];
        for (int t = wid; t < TF+3; t += 4) {
            float a0 = sh[t][lane], a1 = sh[t][lane+32], a2 = sh[t][lane+64], a3 = sh[t][lane+96];
            float s1 = a0+a1+a2+a3;
            float s2 = a0*a0+a1*a1+a2*a2+a3*a3;
            #pragma unroll
            for (int o = 16; o; o >>= 1) {
                s1 += __shfl_xor_sync(0xffffffffu, s1, o);
                s2 += __shfl_xor_sync(0xffffffffu, s2, o);
            }
            float mu = s1 * (1.f/128.f);
            float rs = rsqrtf(s2 * (1.f/128.f) - mu*mu + 1e-5f);
            sh[t][lane]    = (a0-mu)*rs*g0 + b0;
            sh[t][lane+32] = (a1-mu)*rs*g1 + b1;
            sh[t][lane+64] = (a2-mu)*rs*g2 + b2;
            sh[t][lane+96] = (a3-mu)*rs*g3 + b3;
        }
    }
    __syncthreads();

    {
        float cw0 = wcg[c*4], cw1 = wcg[c*4+1], cw2 = wcg[c*4+2], cw3 = wcg[c*4+3];
        float cb = bcg[c];
        float* outp = g_Ug + (size_t)s*LSEQ*128 + c;
        float x0 = 0.f, x1 = 0.f, x2 = 0.f;
        for (int j = 0; j < TF+3; j++) {
            int gl = l0 - 1 + j;
            float xn = (gl >= 0 && gl < LSEQ) ? sh[j][c] : 0.f;
            if (j >= 3) {
                float y = cw0*x0 + cw1*x1 + cw2*x2 + cw3*xn + cb;
                float v = siluf(y);
                outp[(size_t)(l0 + j - 3) * 128] = v;
                sh[j-3][c] = v;
            }
            x0 = x1; x1 = x2; x2 = xn;
        }
    }
    __syncthreads();

    {
        int t = tid >> 2, q = tid & 3;
        u64 accp[9];
        #pragma unroll
        for (int j = 0; j < 9; j++) accp[j] = 0ull;
        const ulonglong2* u2 = (const ulonglong2*)sh[t];
        #pragma unroll
        for (int k4 = 0; k4 < 32; k4++) {
            ulonglong2 uv = u2[k4];
            #pragma unroll
            for (int j = 0; j < 9; j++) {
                ulonglong2 wv = ((const ulonglong2*)swx[q*9 + j])[k4];
                fma2(accp[j], uv.x, wv.x);
                fma2(accp[j], uv.y, wv.y);
            }
        }
        #pragma unroll
        for (int j = 0; j < 9; j++) {
            int r = q*9 + j;
            float v = upksum(accp[j]);
            if (r < 4) sdt[t][r] = v;
            else g_BCg[((size_t)s*LSEQ + l0 + t)*32 + (r-4)] = v;
        }
    }
    __syncthreads();

    for (int i = tid; i < TF*128; i += 128) {
        int t = i >> 7, d = i & 127;
        float x = sdt[t][0]*Wdt[d*4]   + sdt[t][1]*Wdt[d*4+1]
                + sdt[t][2]*Wdt[d*4+2] + sdt[t][3]*Wdt[d*4+3] + bdt[d];
        g_dg[((size_t)s*LSEQ + l0 + t)*128 + d] = softplusf(x);
    }
}

// -------------------- shared staging for scan kernels -----------------------
template<int D, int NT>
__device__ __forceinline__ void stage_tile(
    const float* __restrict__ DEL, const float* __restrict__ U,
    const float* __restrict__ BC, size_t base, int tid,
    float* s_del, float* s_u, float* s_bc)
{
    const float4* gdel = (const float4*)(DEL + base*D);
    const float4* gu   = (const float4*)(U   + base*D);
    const float4* gbc  = (const float4*)(BC  + base*32);
    float4* sdel = (float4*)s_del;
    float4* su4  = (float4*)s_u;
    float4* sbc  = (float4*)s_bc;
    #pragma unroll
    for (int i = 0; i < NT*D/4/128; i++) { int k = i*128 + tid; sdel[k] = gdel[k]; }
    #pragma unroll
    for (int i = 0; i < NT*D/4/128; i++) { int k = i*128 + tid; su4[k]  = gu[k]; }
    #pragma unroll
    for (int k = tid; k < NT*8; k += 128) sbc[k] = gbc[k];
}

// ---------------- scan phase A ------------------------------------------------
template<int D>
__device__ __forceinline__ void scanA_body(
    const float* __restrict__ Alog, float* __restrict__ Sum,
    const float* s_del, const float* s_u, const float* s_bc,
    size_t chunkIdx, int d, int off)
{
    float Ar[16];
    bool st = loadA(Alog, d, Ar);
    float A0 = Ar[0];
    float h[16];
    #pragma unroll
    for (int n = 0; n < 16; n++) h[n] = 0.f;
    float S = 0.f;
    const float4* bc = (const float4*)s_bc;
    #pragma unroll 4
    for (int t = 0; t < TCH; t++) {
        int tt = off + t;
        float del = s_del[tt*D + d];
        float du  = del * s_u[tt*D + d];
        float4 b0 = bc[tt*8+0], b1 = bc[tt*8+1], b2 = bc[tt*8+2], b3 = bc[tt*8+3];
        float a[16];
        if (st) powers16(__expf(del*A0), a);
        else {
            #pragma unroll
            for (int n = 0; n < 16; n++) a[n] = __expf(del*Ar[n]);
        }
        h[0]=a[0]*h[0]+du*b0.x;  h[1]=a[1]*h[1]+du*b0.y;
        h[2]=a[2]*h[2]+du*b0.z;  h[3]=a[3]*h[3]+du*b0.w;
        h[4]=a[4]*h[4]+du*b1.x;  h[5]=a[5]*h[5]+du*b1.y;
        h[6]=a[6]*h[6]+du*b1.z;  h[7]=a[7]*h[7]+du*b1.w;
        h[8]=a[8]*h[8]+du*b2.x;  h[9]=a[9]*h[9]+du*b2.y;
        h[10]=a[10]*h[10]+du*b2.z; h[11]=a[11]*h[11]+du*b2.w;
        h[12]=a[12]*h[12]+du*b3.x; h[13]=a[13]*h[13]+du*b3.y;
        h[14]=a[14]*h[14]+du*b3.z; h[15]=a[15]*h[15]+du*b3.w;
        S += del;
    }
    float ap[16];
    if (st) powers16(__expf(S*A0), ap);
    else {
        #pragma unroll
        for (int n = 0; n < 16; n++) ap[n] = __expf(S*Ar[n]);
    }
    float4* o = (float4*)(Sum + (chunkIdx*D + d)*32);
    float4* hv = (float4*)h;
    float4* av = (float4*)ap;
    #pragma unroll
    for (int n = 0; n < 4; n++) { o[n] = hv[n]; o[4+n] = av[n]; }
}

__global__ void __launch_bounds__(128) k_scanA_m(const float* __restrict__ Alog_m)
{
    __shared__ __align__(16) float s_del[2*TCH*64];
    __shared__ __align__(16) float s_u  [2*TCH*64];
    __shared__ __align__(16) float s_bc [2*TCH*32];
    int tid = threadIdx.x;
    int bid = blockIdx.x;
    int s = bid / (NCHK/2), cp = bid - s*(NCHK/2);
    size_t base = (size_t)s*LSEQ + (size_t)cp*(2*TCH);
    stage_tile<64,2*TCH>(g_dm, g_Um, g_BCm, base, tid, s_del, s_u, s_bc);
    __syncthreads();
    int half = tid >> 6, d = tid & 63;
    scanA_body<64>(Alog_m, g_SumM, s_del, s_u, s_bc,
                   (size_t)s*NCHK + cp*2 + half, d, half*TCH);
}

__global__ void __launch_bounds__(128) k_scanA_g(const float* __restrict__ Alog_g)
{
    __shared__ __align__(16) float s_del[TCH*128];
    __shared__ __align__(16) float s_u  [TCH*128];
    __shared__ __align__(16) float s_bc [TCH*32];
    int tid = threadIdx.x;
    int bid = blockIdx.x;
    int s = bid / NCHK, ch = bid - s*NCHK;
    size_t base = (size_t)s*LSEQ + (size_t)ch*TCH;
    stage_tile<128,TCH>(g_dg, g_Ug, g_BCg, base, tid, s_del, s_u, s_bc);
    __syncthreads();
    scanA_body<128>(Alog_g, g_SumG, s_del, s_u, s_bc,
                    (size_t)s*NCHK + ch, tid, 0);
}

// ============ scan phase B: hierarchical prefix ===============
template<int D>
__device__ __forceinline__ void scanB1_body(int t)
{
    const float* Sum = (D == 64) ? g_SumM : g_SumG;
    float* GA = (D == 64) ? g_GAm : g_GAg;
    float* GB = (D == 64) ? g_GBm : g_GBg;
    int n = t & 15;
    int g = (t >> 4) % NGRP;
    int rest = t / (16*NGRP);
    int d = rest % D, s = rest / D;
    const float* p = Sum + (((size_t)s*NCHK + g*GSZ)*D + d)*32 + n;
    float A = 1.f, B = 0.f;
    #pragma unroll 4
    for (int c = 0; c < GSZ; c++) {
        float b = p[(size_t)c*D*32];
        float a = p[(size_t)c*D*32 + 16];
        A = a*A; B = a*B + b;
    }
    size_t gi = (((size_t)s*NGRP + g)*D + d)*16 + n;
    GA[gi] = A; GB[gi] = B;
}
__global__ void __launch_bounds__(256) k_scanB1_m()
{
    int t = blockIdx.x * 256 + threadIdx.x;
    if (t < 4*64*16*NGRP) scanB1_body<64>(t);
}
__global__ void __launch_bounds__(256) k_scanB1_g()
{
    int t = blockIdx.x * 256 + threadIdx.x;
    if (t < 4*128*16*NGRP) scanB1_body<128>(t);
}
template<int D>
__device__ __forceinline__ void scanB2_body(int t)
{
    const float* GA = (D == 64) ? g_GAm : g_GAg;
    const float* GB = (D == 64) ? g_GBm : g_GBg;
    float* GH = (D == 64) ? g_GHm : g_GHg;
    int n = t & 15;
    int d = (t >> 4) % D;
    int s = t / (D*16);
    size_t stride = (size_t)D*16;
    size_t base = ((size_t)s*NGRP*D + d)*16 + n;
    float P = 0.f;
    #pragma unroll 3
    for (int g = 0; g < NGRP; g++) {
        size_t gi = base + (size_t)g*stride;
        GH[gi] = P;
        P = GA[gi]*P + GB[gi];
    }
}
__global__ void __launch_bounds__(256) k_scanB2_m()
{
    int t = blockIdx.x * 256 + threadIdx.x;
    if (t < 4*64*16) scanB2_body<64>(t);
}
__global__ void __launch_bounds__(256) k_scanB2_g()
{
    int t = blockIdx.x * 256 + threadIdx.x;
    if (t < 4*128*16) scanB2_body<128>(t);
}
template<int D>
__device__ __forceinline__ void scanB3_body(int t)
{
    const float* Sum = (D == 64) ? g_SumM : g_SumG;
    const float* GH  = (D == 64) ? g_GHm : g_GHg;
    float* Hin = (D == 64) ? g_HinM : g_HinG;
    int n = t & 15;
    int g = (t >> 4) % NGRP;
    int rest = t / (16*NGRP);
    int d = rest % D, s = rest / D;
    float hin = GH[(((size_t)s*NGRP + g)*D + d)*16 + n];
    const float* p = Sum + (((size_t)s*NCHK + g*GSZ)*D + d)*32 + n;
    float* hp = Hin + (((size_t)s*NCHK + g*GSZ)*D + d)*16 + n;
    #pragma unroll 4
    for (int c = 0; c < GSZ; c++) {
        hp[(size_t)c*D*16] = hin;
        float b = p[(size_t)c*D*32];
        float a = p[(size_t)c*D*32 + 16];
        hin = a*hin + b;
    }
}
__global__ void __launch_bounds__(256) k_scanB3_m()
{
    int t = blockIdx.x * 256 + threadIdx.x;
    if (t < 4*64*16*NGRP) scanB3_body<64>(t);
}
__global__ void __launch_bounds__(256) k_scanB3_g()
{
    int t = blockIdx.x * 256 + threadIdx.x;
    if (t < 4*128*16*NGRP) scanB3_body<128>(t);
}

// ---------------- scan phase C ------------------------------------------------
template<int D>
__device__ __forceinline__ void scanC_body(
    const float* __restrict__ Alog, const float* __restrict__ Dp,
    const float* __restrict__ Hin, float* __restrict__ Y,
    const float* s_del, const float* s_u, const float* s_bc,
    size_t chunkIdx, int d, int off, size_t base)
{
    float Ar[16];
    bool st = loadA(Alog, d, Ar);
    float A0 = Ar[0];
    float h[16];
    const float4* hp = (const float4*)(Hin + (chunkIdx*D + d)*16);
    float4 h0 = hp[0], h1 = hp[1], h2 = hp[2], h3 = hp[3];
    h[0]=h0.x; h[1]=h0.y; h[2]=h0.z; h[3]=h0.w;
    h[4]=h1.x; h[5]=h1.y; h[6]=h1.z; h[7]=h1.w;
    h[8]=h2.x; h[9]=h2.y; h[10]=h2.z; h[11]=h2.w;
    h[12]=h3.x; h[13]=h3.y; h[14]=h3.z; h[15]=h3.w;
    float Dd = Dp[d];
    const float4* bc = (const float4*)s_bc;
    float* yp = Y + (base + off)*D + d;
    #pragma unroll 4
    for (int t = 0; t < TCH; t++) {
        int tt = off + t;
        float del = s_del[tt*D + d];
        float u   = s_u  [tt*D + d];
        float du  = del * u;
        float4 b0 = bc[tt*8+0], b1 = bc[tt*8+1], b2 = bc[tt*8+2], b3 = bc[tt*8+3];
        float4 c0 = bc[tt*8+4], c1 = bc[tt*8+5], c2 = bc[tt*8+6], c3 = bc[tt*8+7];
        float a[16];
        if (st) powers16(__expf(del*A0), a);
        else {
            #pragma unroll
            for (int n = 0; n < 16; n++) a[n] = __expf(del*Ar[n]);
        }
        h[0]=a[0]*h[0]+du*b0.x;  h[1]=a[1]*h[1]+du*b0.y;
        h[2]=a[2]*h[2]+du*b0.z;  h[3]=a[3]*h[3]+du*b0.w;
        h[4]=a[4]*h[4]+du*b1.x;  h[5]=a[5]*h[5]+du*b1.y;
        h[6]=a[6]*h[6]+du*b1.z;  h[7]=a[7]*h[7]+du*b1.w;
        h[8]=a[8]*h[8]+du*b2.x;  h[9]=a[9]*h[9]+du*b2.y;
        h[10]=a[10]*h[10]+du*b2.z; h[11]=a[11]*h[11]+du*b2.w;
        h[12]=a[12]*h[12]+du*b3.x; h[13]=a[13]*h[13]+du*b3.y;
        h[14]=a[14]*h[14]+du*b3.z; h[15]=a[15]*h[15]+du*b3.w;
        float y = Dd*u;
        y += h[0]*c0.x + h[1]*c0.y + h[2]*c0.z + h[3]*c0.w;
        y += h[4]*c1.x + h[5]*c1.y + h[6]*c1.z + h[7]*c1.w;
        y += h[8]*c2.x + h[9]*c2.y + h[10]*c2.z + h[11]*c2.w;
        y += h[12]*c3.x + h[13]*c3.y + h[14]*c3.z + h[15]*c3.w;
        yp[(size_t)t*D] = y;
    }
}

__global__ void __launch_bounds__(128) k_scanC_m(
    const float* __restrict__ Alog_m, const float* __restrict__ Dm)
{
    __shared__ __align__(16) float s_del[2*TCH*64];
    __shared__ __align__(16) float s_u  [2*TCH*64];
    __shared__ __align__(16) float s_bc [2*TCH*32];
    int tid = threadIdx.x;
    int bid = blockIdx.x;
    int s = bid / (NCHK/2), cp = bid - s*(NCHK/2);
    size_t base = (size_t)s*LSEQ + (size_t)cp*(2*TCH);
    stage_tile<64,2*TCH>(g_dm, g_Um, g_BCm, base, tid, s_del, s_u, s_bc);
    __syncthreads();
    int half = tid >> 6, d = tid & 63;
    scanC_body<64>(Alog_m, Dm, g_HinM, g_ym, s_del, s_u, s_bc,
                   (size_t)s*NCHK + cp*2 + half, d, half*TCH, base);
}

__global__ void __launch_bounds__(128) k_scanC_g(
    const float* __restrict__ Alog_g, const float* __restrict__ Dg)
{
    __shared__ __align__(16) float s_del[TCH*128];
    __shared__ __align__(16) float s_u  [TCH*128];
    __shared__ __align__(16) float s_bc [TCH*32];
    int tid = threadIdx.x;
    int bid = blockIdx.x;
    int s = bid / NCHK, ch = bid - s*NCHK;
    size_t base = (size_t)s*LSEQ + (size_t)ch*TCH;
    stage_tile<128,TCH>(g_dg, g_Ug, g_BCg, base, tid, s_del, s_u, s_bc);
    __syncthreads();
    scanC_body<128>(Alog_g, Dg, g_HinG, g_yg, s_del, s_u, s_bc,
                    (size_t)s*NCHK + ch, tid, 0, base);
}

// ---------------- output: o = (mixer ⊙ global) @ Wo^T + bo (packed) ---------
__global__ void __launch_bounds__(256) k_out(
    const float* __restrict__ Wo, const float* __restrict__ bo,
    float* __restrict__ out)
{
    __shared__ __align__(16) float sp[64*132];
    int o = blockIdx.y >> 1, b = blockIdx.y & 1;
    int l0 = blockIdx.x * 64;
    int tid = threadIdx.x;

    int sm = (o == 0) ? b : 2 + b;
    int sg = (o == 0) ? 2 + b : b;
    const float* ym = g_ym + ((size_t)sm*LSEQ + l0)*64;
    const float* zz = g_Z  + ((size_t)sm*LSEQ + l0)*64;
    const float* yg = g_yg + ((size_t)sg*LSEQ + l0)*128;

    for (int i = tid; i < 64*128; i += 256) {
        int t = i >> 7, k = i & 127;
        float m = (k < 64) ? ym[t*64 + k] : zz[t*64 + (k-64)];
        sp[t*132 + k] = m * yg[t*128 + k];
    }
    __syncthreads();

    int tx = tid & 15, ty = tid >> 4;
    int ch0 = tx * 4, t0 = ty * 4;
    u64 acc[4][4];
    #pragma unroll
    for (int i = 0; i < 4; i++)
        #pragma unroll
        for (int j = 0; j < 4; j++) acc[i][j] = 0ull;

    const ulonglong2* p0 = (const ulonglong2*)(sp + (t0+0)*132);
    const ulonglong2* p1 = (const ulonglong2*)(sp + (t0+1)*132);
    const ulonglong2* p2 = (const ulonglong2*)(sp + (t0+2)*132);
    const ulonglong2* p3 = (const ulonglong2*)(sp + (t0+3)*132);
    const ulonglong2* w0 = (const ulonglong2*)(Wo + (ch0+0)*128);
    const ulonglong2* w1 = (const ulonglong2*)(Wo + (ch0+1)*128);
    const ulonglong2* w2 = (const ulonglong2*)(Wo + (ch0+2)*128);
    const ulonglong2* w3 = (const ulonglong2*)(Wo + (ch0+3)*128);
    #pragma unroll 8
    for (int k4 = 0; k4 < 32; k4++) {
        ulonglong2 pv[4] = { p0[k4], p1[k4], p2[k4], p3[k4] };
        ulonglong2 wv[4] = { __ldg(w0+k4), __ldg(w1+k4), __ldg(w2+k4), __ldg(w3+k4) };
        #pragma unroll
        for (int i = 0; i < 4; i++)
            #pragma unroll
            for (int j = 0; j < 4; j++) {
                fma2(acc[i][j], pv[i].x, wv[j].x);
                fma2(acc[i][j], pv[i].y, wv[j].y);
            }
    }
    float* op = out + ((size_t)o*2 + b)*64*LSEQ;
    #pragma unroll
    for (int j = 0; j < 4; j++) {
        float bj = bo[ch0 + j];
        float4 v = { upksum(acc[0][j])+bj, upksum(acc[1][j])+bj,
                     upksum(acc[2][j])+bj, upksum(acc[3][j])+bj };
        *(float4*)(op + (size_t)(ch0+j)*LSEQ + l0 + t0) = v;
    }
}

// -----------------------------------------------------------------------------
extern "C" void kernel_launch(void* const* d_in, const int* in_sizes, int n_in,
                              void* d_out, int out_size)
{
    const float* f1    = (const float*)d_in[0];
    const float* f2    = (const float*)d_in[1];
    const float* Wi    = (const float*)d_in[2];
    const float* bi    = (const float*)d_in[3];
    const float* wcx   = (const float*)d_in[4];
    const float* bcx   = (const float*)d_in[5];
    const float* wcz   = (const float*)d_in[6];
    const float* bcz   = (const float*)d_in[7];
    const float* Wxp_m = (const float*)d_in[8];
    const float* Wdt_m = (const float*)d_in[9];
    const float* bdt_m = (const float*)d_in[10];
    const float* Alog_m= (const float*)d_in[11];
    const float* Dm    = (const float*)d_in[12];
    const float* Wg    = (const float*)d_in[13];
    const float* bg    = (const float*)d_in[14];
    const float* ln_g  = (const float*)d_in[15];
    const float* ln_b  = (const float*)d_in[16];
    const float* wcg   = (const float*)d_in[17];
    const float* bcg   = (const float*)d_in[18];
    const float* Wxp_g = (const float*)d_in[19];
    const float* Wdt_g = (const float*)d_in[20];
    const float* bdt_g = (const float*)d_in[21];
    const float* Alog_g= (const float*)d_in[22];
    const float* Dg    = (const float*)d_in[23];
    const float* Wo    = (const float*)d_in[24];
    const float* bo    = (const float*)d_in[25];
    float* out = (float*)d_out;

    // one-time stream/event setup (first call = uncaptured correctness run)
    static cudaStream_t s_mix = nullptr;
    static cudaEvent_t ev_fork = nullptr, ev_join = nullptr;
    if (s_mix == nullptr) {
        cudaStreamCreateWithFlags(&s_mix, cudaStreamNonBlocking);
        cudaEventCreateWithFlags(&ev_fork, cudaEventDisableTiming);
        cudaEventCreateWithFlags(&ev_join, cudaEventDisableTiming);
    }

    // fork: mixer chain on s_mix, global chain on the launch stream
    cudaEventRecord(ev_fork, 0);
    cudaStreamWaitEvent(s_mix, ev_fork, 0);

    // mixer chain (short)
    k_mixer_front <<<dim3(4, LSEQ/64), 128, 0, s_mix>>>(
        f1, f2, Wi, bi, wcx, bcx, wcz, bcz, Wxp_m, Wdt_m, bdt_m);
    k_scanA_m  <<<4*(NCHK/2), 128, 0, s_mix>>>(Alog_m);
    k_scanB1_m <<<(4*64*16*NGRP + 255)/256, 256, 0, s_mix>>>();
    k_scanB2_m <<<(4*64*16 + 255)/256, 256, 0, s_mix>>>();
    k_scanB3_m <<<(4*64*16*NGRP + 255)/256, 256, 0, s_mix>>>();
    k_scanC_m  <<<4*(NCHK/2), 128, 0, s_mix>>>(Alog_m, Dm);
    cudaEventRecord(ev_join, s_mix);

    // global chain (long) on the default/captured stream
    k_global_front<<<dim3(4, LSEQ/32), 128>>>(
        f1, f2, Wg, bg, ln_g, ln_b, wcg, bcg, Wxp_g, Wdt_g, bdt_g);
    k_scanA_g  <<<4*NCHK, 128>>>(Alog_g);
    k_scanB1_g <<<(4*128*16*NGRP + 255)/256, 256>>>();
    k_scanB2_g <<<(4*128*16 + 255)/256, 256>>>();
    k_scanB3_g <<<(4*128*16*NGRP + 255)/256, 256>>>();
    k_scanC_g  <<<4*NCHK, 128>>>(Alog_g, Dg);

    // join and emit output
    cudaStreamWaitEvent(0, ev_join, 0);
    k_out <<<dim3(LSEQ/64, 4), 256>>>(Wo, bo, out);
}

// round 17
// speedup vs baseline: 1.1883x; 1.0285x over previous
#include <cuda_runtime.h>
#include <math.h>

#define LSEQ 9216
#define NCHK 288
#define TCH  32
#define NGRP 18
#define GSZ  16

typedef unsigned long long u64;

// ------------------------- scratch (device globals) -------------------------
__device__ __align__(16) float g_Um [4*LSEQ*64];
__device__ __align__(16) float g_Z  [4*LSEQ*64];
__device__ __align__(16) float g_dm [4*LSEQ*64];
__device__ __align__(16) float g_BCm[4*LSEQ*32];
__device__ __align__(16) float g_ym [4*LSEQ*64];
__device__ __align__(16) float g_Ug [4*LSEQ*128];
__device__ __align__(16) float g_dg [4*LSEQ*128];
__device__ __align__(16) float g_BCg[4*LSEQ*32];
__device__ __align__(16) float g_yg [4*LSEQ*128];
__device__ __align__(16) float g_SumM[4*NCHK*64*32];
__device__ __align__(16) float g_SumG[(size_t)4*NCHK*128*32];
__device__ __align__(16) float g_HinM[4*NCHK*64*16];
__device__ __align__(16) float g_HinG[4*NCHK*128*16];
__device__ __align__(16) float g_GAm[4*NGRP*64*16];
__device__ __align__(16) float g_GBm[4*NGRP*64*16];
__device__ __align__(16) float g_GHm[4*NGRP*64*16];
__device__ __align__(16) float g_GAg[4*NGRP*128*16];
__device__ __align__(16) float g_GBg[4*NGRP*128*16];
__device__ __align__(16) float g_GHg[4*NGRP*128*16];

__device__ __forceinline__ float siluf(float y) {
    return y / (1.f + __expf(-y));
}
__device__ __forceinline__ float softplusf(float x) {
    return (x > 20.f) ? x : log1pf(expf(x));
}
// ---- packed f32x2 helpers ----
__device__ __forceinline__ void fma2(u64& d, u64 a, u64 b) {
    asm("fma.rn.f32x2 %0, %1, %2, %0;" : "+l"(d) : "l"(a), "l"(b));
}
__device__ __forceinline__ float upksum(u64 v) {
    float lo, hi;
    asm("mov.b64 {%0,%1}, %2;" : "=f"(lo), "=f"(hi) : "l"(v));
    return lo + hi;
}
__device__ __forceinline__ float dot64p(const float* rowf, const u64* w2) {
    const ulonglong2* row = (const ulonglong2*)rowf;
    u64 a0 = 0ull, a1 = 0ull, a2 = 0ull, a3 = 0ull;
    #pragma unroll
    for (int k = 0; k < 16; k += 4) {
        ulonglong2 r0 = row[k],   r1 = row[k+1];
        ulonglong2 r2 = row[k+2], r3 = row[k+3];
        fma2(a0, r0.x, w2[2*k+0]); fma2(a1, r0.y, w2[2*k+1]);
        fma2(a2, r1.x, w2[2*k+2]); fma2(a3, r1.y, w2[2*k+3]);
        fma2(a0, r2.x, w2[2*k+4]); fma2(a1, r2.y, w2[2*k+5]);
        fma2(a2, r3.x, w2[2*k+6]); fma2(a3, r3.y, w2[2*k+7]);
    }
    return (upksum(a0) + upksum(a1)) + (upksum(a2) + upksum(a3));
}
__device__ __forceinline__ void powers16(float e1, float* pw) {
    pw[0]=e1;
    pw[1]=pw[0]*pw[0];  pw[2]=pw[1]*pw[0];  pw[3]=pw[1]*pw[1];
    pw[4]=pw[2]*pw[1];  pw[5]=pw[2]*pw[2];  pw[6]=pw[3]*pw[2];  pw[7]=pw[3]*pw[3];
    pw[8]=pw[4]*pw[3];  pw[9]=pw[4]*pw[4];  pw[10]=pw[5]*pw[4]; pw[11]=pw[5]*pw[5];
    pw[12]=pw[6]*pw[5]; pw[13]=pw[6]*pw[6]; pw[14]=pw[7]*pw[6]; pw[15]=pw[7]*pw[7];
}
__device__ __forceinline__ bool loadA(const float* Alog, int d, float* Ar) {
    #pragma unroll
    for (int n = 0; n < 16; n++) Ar[n] = -__expf(Alog[d*16 + n]);
    bool st = true;
    #pragma unroll
    for (int n = 1; n < 16; n++)
        if (fabsf(Ar[n] - (float)(n+1)*Ar[0]) > 1e-4f * fabsf(Ar[n])) st = false;
    return st;
}

// ======== mixer front: GEMM + dwconv + silu + FUSED proj/delta ==============
__global__ void __launch_bounds__(128) k_mixer_front(
    const float* __restrict__ f1, const float* __restrict__ f2,
    const float* __restrict__ Wi, const float* __restrict__ bi,
    const float* __restrict__ wcx, const float* __restrict__ bcx,
    const float* __restrict__ wcz, const float* __restrict__ bcz,
    const float* __restrict__ Wxp, const float* __restrict__ Wdt,
    const float* __restrict__ bdt)
{
    const int TF = 64;
    __shared__ __align__(16) float sx[TF+3][64];
    __shared__ __align__(16) float su[TF][68];
    __shared__ __align__(16) float swx[36][68];
    __shared__ float sdt[TF][4];
    int s = blockIdx.x;
    const float* f = ((s >> 1) ? f2 : f1) + (size_t)(s & 1) * 64 * LSEQ;
    int l0 = blockIdx.y * TF;
    int tid = threadIdx.x, lane = tid & 31, w4 = tid >> 5;

    {
        float (*tmp)[TF+3] = (float(*)[TF+3])su;
        for (int r = w4; r < 64; r += 4) {
            const float* fr = f + (size_t)r*LSEQ + l0 - 1;
            #pragma unroll
            for (int j = lane; j < TF+3; j += 32) {
                int gl = l0 - 1 + j;
                tmp[r][j] = (gl >= 0 && gl < LSEQ) ? fr[j] : 0.f;
            }
        }
        for (int i = tid; i < 36*64; i += 128) swx[i >> 6][i & 63] = Wxp[i];
        __syncthreads();
        for (int j = w4; j < TF+3; j += 4) {
            sx[j][lane]      = tmp[lane][j];
            sx[j][lane + 32] = tmp[lane + 32][j];
        }
    }
    __syncthreads();

    int c = tid;
    {
        u64 w2[32];
        const ulonglong2* wrow = (const ulonglong2*)(Wi + c*64);
        #pragma unroll
        for (int i = 0; i < 16; i++) { ulonglong2 t = wrow[i]; w2[2*i] = t.x; w2[2*i+1] = t.y; }
        float bias = bi[c];
        const float* cw = (c < 64) ? (wcx + c*4) : (wcz + (c-64)*4);
        float cw0 = cw[0], cw1 = cw[1], cw2 = cw[2], cw3 = cw[3];
        float cb = (c < 64) ? bcx[c] : bcz[c-64];
        bool isx = (c < 64);
        float* outp = isx ? (g_Um + (size_t)s*LSEQ*64 + c)
                          : (g_Z  + (size_t)s*LSEQ*64 + (c-64));
        float x0 = 0.f, x1 = 0.f, x2 = 0.f;
        #pragma unroll 2
        for (int j = 0; j < TF+3; j++) {
            int gl = l0 - 1 + j;
            float acc = bias + dot64p(sx[j], w2);
            if (gl < 0 || gl >= LSEQ) acc = 0.f;
            if (j >= 3) {
                float y = cw0*x0 + cw1*x1 + cw2*x2 + cw3*acc + cb;
                float v = siluf(y);
                outp[(size_t)(l0 + j - 3) * 64] = v;
                if (isx) su[j-3][c] = v;
            }
            x0 = x1; x1 = x2; x2 = acc;
        }
    }
    __syncthreads();

    {
        int q = tid & 3;
        #pragma unroll
        for (int p = 0; p < 2; p++) {
            int t = p*32 + (tid >> 2);
            u64 accp[9];
            #pragma unroll
            for (int j = 0; j < 9; j++) accp[j] = 0ull;
            const ulonglong2* u2 = (const ulonglong2*)su[t];
            #pragma unroll
            for (int k4 = 0; k4 < 16; k4++) {
                ulonglong2 uv = u2[k4];
                #pragma unroll
                for (int j = 0; j < 9; j++) {
                    ulonglong2 wv = ((const ulonglong2*)swx[q*9 + j])[k4];
                    fma2(accp[j], uv.x, wv.x);
                    fma2(accp[j], uv.y, wv.y);
                }
            }
            #pragma unroll
            for (int j = 0; j < 9; j++) {
                int r = q*9 + j;
                float v = upksum(accp[j]);
                if (r < 4) sdt[t][r] = v;
                else g_BCm[((size_t)s*LSEQ + l0 + t)*32 + (r-4)] = v;
            }
        }
    }
    __syncthreads();

    for (int i = tid; i < TF*64; i += 128) {
        int t = i >> 6, d = i & 63;
        float x = sdt[t][0]*Wdt[d*4]   + sdt[t][1]*Wdt[d*4+1]
                + sdt[t][2]*Wdt[d*4+2] + sdt[t][3]*Wdt[d*4+3] + bdt[d];
        g_dm[((size_t)s*LSEQ + l0 + t)*64 + d] = softplusf(x);
    }
}

// ======== global front: GEMM + LN + dwconv + silu + FUSED proj/delta ========
__global__ void __launch_bounds__(128) k_global_front(
    const float* __restrict__ f1, const float* __restrict__ f2,
    const float* __restrict__ Wg, const float* __restrict__ bg,
    const float* __restrict__ ln_g, const float* __restrict__ ln_b,
    const float* __restrict__ wcg, const float* __restrict__ bcg,
    const float* __restrict__ Wxp, const float* __restrict__ Wdt,
    const float* __restrict__ bdt)
{
    const int TF = 32;
    __shared__ __align__(16) float sh[TF+3][132];
    __shared__ __align__(16) float sbuf[36*132];
    __shared__ float sdt[TF][4];
    float (*sx)[64]   = (float(*)[64])sbuf;
    float (*swx)[132] = (float(*)[132])sbuf;
    int s = blockIdx.x;
    const float* f = ((s >> 1) ? f2 : f1) + (size_t)(s & 1) * 64 * LSEQ;
    int l0 = blockIdx.y * TF;
    int tid = threadIdx.x, lane = tid & 31, wid = tid >> 5;

    {
        float (*tmp)[TF+3] = (float(*)[TF+3])(sbuf + 2496);
        for (int r = wid; r < 64; r += 4) {
            const float* fr = f + (size_t)r*LSEQ + l0 - 1;
            #pragma unroll
            for (int j = lane; j < TF+3; j += 32) {
                int gl = l0 - 1 + j;
                tmp[r][j] = (gl >= 0 && gl < LSEQ) ? fr[j] : 0.f;
            }
        }
        __syncthreads();
        for (int j = wid; j < TF+3; j += 4) {
            sx[j][lane]      = tmp[lane][j];
            sx[j][lane + 32] = tmp[lane + 32][j];
        }
    }
    __syncthreads();

    int c = tid;
    {
        u64 w2[32];
        const ulonglong2* wrow = (const ulonglong2*)(Wg + c*64);
        #pragma unroll
        for (int i = 0; i < 16; i++) { ulonglong2 t = wrow[i]; w2[2*i] = t.x; w2[2*i+1] = t.y; }
        float bias = bg[c];
        #pragma unroll 2
        for (int j = 0; j < TF+3; j++)
            sh[j][c] = bias + dot64p(sx[j], w2);
    }
    __syncthreads();

    for (int i = tid; i < 36*128; i += 128) swx[i >> 7][i & 127] = Wxp[i];

    {
        float g0 = ln_g[lane],    g1 = ln_g[lane+32], g2 = ln_g[lane+64], g3 = ln_g[lane+96];
        float b0 = ln_b[lane],    b1 = ln_b[lane+32], b2 = ln_b[lane+64], b3 = ln_b[lane+96];
        for (int t = wid; t < TF+3; t += 4) {
            float a0 = sh[t][lane], a1 = sh[t][lane+32], a2 = sh[t][lane+64], a3 = sh[t][lane+96];
            float s1 = a0+a1+a2+a3;
            float s2 = a0*a0+a1*a1+a2*a2+a3*a3;
            #pragma unroll
            for (int o = 16; o; o >>= 1) {
                s1 += __shfl_xor_sync(0xffffffffu, s1, o);
                s2 += __shfl_xor_sync(0xffffffffu, s2, o);
            }
            float mu = s1 * (1.f/128.f);
            float rs = rsqrtf(s2 * (1.f/128.f) - mu*mu + 1e-5f);
            sh[t][lane]    = (a0-mu)*rs*g0 + b0;
            sh[t][lane+32] = (a1-mu)*rs*g1 + b1;
            sh[t][lane+64] = (a2-mu)*rs*g2 + b2;
            sh[t][lane+96] = (a3-mu)*rs*g3 + b3;
        }
    }
    __syncthreads();

    {
        float cw0 = wcg[c*4], cw1 = wcg[c*4+1], cw2 = wcg[c*4+2], cw3 = wcg[c*4+3];
        float cb = bcg[c];
        float* outp = g_Ug + (size_t)s*LSEQ*128 + c;
        float x0 = 0.f, x1 = 0.f, x2 = 0.f;
        for (int j = 0; j < TF+3; j++) {
            int gl = l0 - 1 + j;
            float xn = (gl >= 0 && gl < LSEQ) ? sh[j][c] : 0.f;
            if (j >= 3) {
                float y = cw0*x0 + cw1*x1 + cw2*x2 + cw3*xn + cb;
                float v = siluf(y);
                outp[(size_t)(l0 + j - 3) * 128] = v;
                sh[j-3][c] = v;
            }
            x0 = x1; x1 = x2; x2 = xn;
        }
    }
    __syncthreads();

    {
        int t = tid >> 2, q = tid & 3;
        u64 accp[9];
        #pragma unroll
        for (int j = 0; j < 9; j++) accp[j] = 0ull;
        const ulonglong2* u2 = (const ulonglong2*)sh[t];
        #pragma unroll
        for (int k4 = 0; k4 < 32; k4++) {
            ulonglong2 uv = u2[k4];
            #pragma unroll
            for (int j = 0; j < 9; j++) {
                ulonglong2 wv = ((const ulonglong2*)swx[q*9 + j])[k4];
                fma2(accp[j], uv.x, wv.x);
                fma2(accp[j], uv.y, wv.y);
            }
        }
        #pragma unroll
        for (int j = 0; j < 9; j++) {
            int r = q*9 + j;
            float v = upksum(accp[j]);
            if (r < 4) sdt[t][r] = v;
            else g_BCg[((size_t)s*LSEQ + l0 + t)*32 + (r-4)] = v;
        }
    }
    __syncthreads();

    for (int i = tid; i < TF*128; i += 128) {
        int t = i >> 7, d = i & 127;
        float x = sdt[t][0]*Wdt[d*4]   + sdt[t][1]*Wdt[d*4+1]
                + sdt[t][2]*Wdt[d*4+2] + sdt[t][3]*Wdt[d*4+3] + bdt[d];
        g_dg[((size_t)s*LSEQ + l0 + t)*128 + d] = softplusf(x);
    }
}

// -------------------- shared staging for scan kernels -----------------------
template<int D, int NT>
__device__ __forceinline__ void stage_tile(
    const float* __restrict__ DEL, const float* __restrict__ U,
    const float* __restrict__ BC, size_t base, int tid,
    float* s_del, float* s_u, float* s_bc)
{
    const float4* gdel = (const float4*)(DEL + base*D);
    const float4* gu   = (const float4*)(U   + base*D);
    const float4* gbc  = (const float4*)(BC  + base*32);
    float4* sdel = (float4*)s_del;
    float4* su4  = (float4*)s_u;
    float4* sbc  = (float4*)s_bc;
    #pragma unroll
    for (int i = 0; i < NT*D/4/128; i++) { int k = i*128 + tid; sdel[k] = gdel[k]; }
    #pragma unroll
    for (int i = 0; i < NT*D/4/128; i++) { int k = i*128 + tid; su4[k]  = gu[k]; }
    #pragma unroll
    for (int k = tid; k < NT*8; k += 128) sbc[k] = gbc[k];
}

// ---------------- scan phase A ------------------------------------------------
template<int D>
__device__ __forceinline__ void scanA_body(
    const float* __restrict__ Alog, float* __restrict__ Sum,
    const float* s_del, const float* s_u, const float* s_bc,
    size_t chunkIdx, int d, int off)
{
    float Ar[16];
    bool st = loadA(Alog, d, Ar);
    float A0 = Ar[0];
    float h[16];
    #pragma unroll
    for (int n = 0; n < 16; n++) h[n] = 0.f;
    float S = 0.f;
    const float4* bc = (const float4*)s_bc;
    #pragma unroll 4
    for (int t = 0; t < TCH; t++) {
        int tt = off + t;
        float del = s_del[tt*D + d];
        float du  = del * s_u[tt*D + d];
        float4 b0 = bc[tt*8+0], b1 = bc[tt*8+1], b2 = bc[tt*8+2], b3 = bc[tt*8+3];
        float a[16];
        if (st) powers16(__expf(del*A0), a);
        else {
            #pragma unroll
            for (int n = 0; n < 16; n++) a[n] = __expf(del*Ar[n]);
        }
        h[0]=a[0]*h[0]+du*b0.x;  h[1]=a[1]*h[1]+du*b0.y;
        h[2]=a[2]*h[2]+du*b0.z;  h[3]=a[3]*h[3]+du*b0.w;
        h[4]=a[4]*h[4]+du*b1.x;  h[5]=a[5]*h[5]+du*b1.y;
        h[6]=a[6]*h[6]+du*b1.z;  h[7]=a[7]*h[7]+du*b1.w;
        h[8]=a[8]*h[8]+du*b2.x;  h[9]=a[9]*h[9]+du*b2.y;
        h[10]=a[10]*h[10]+du*b2.z; h[11]=a[11]*h[11]+du*b2.w;
        h[12]=a[12]*h[12]+du*b3.x; h[13]=a[13]*h[13]+du*b3.y;
        h[14]=a[14]*h[14]+du*b3.z; h[15]=a[15]*h[15]+du*b3.w;
        S += del;
    }
    float ap[16];
    if (st) powers16(__expf(S*A0), ap);
    else {
        #pragma unroll
        for (int n = 0; n < 16; n++) ap[n] = __expf(S*Ar[n]);
    }
    float4* o = (float4*)(Sum + (chunkIdx*D + d)*32);
    float4* hv = (float4*)h;
    float4* av = (float4*)ap;
    #pragma unroll
    for (int n = 0; n < 4; n++) { o[n] = hv[n]; o[4+n] = av[n]; }
}

__global__ void __launch_bounds__(128) k_scanA_m(const float* __restrict__ Alog_m)
{
    __shared__ __align__(16) float s_del[2*TCH*64];
    __shared__ __align__(16) float s_u  [2*TCH*64];
    __shared__ __align__(16) float s_bc [2*TCH*32];
    int tid = threadIdx.x;
    int bid = blockIdx.x;
    int s = bid / (NCHK/2), cp = bid - s*(NCHK/2);
    size_t base = (size_t)s*LSEQ + (size_t)cp*(2*TCH);
    stage_tile<64,2*TCH>(g_dm, g_Um, g_BCm, base, tid, s_del, s_u, s_bc);
    __syncthreads();
    int half = tid >> 6, d = tid & 63;
    scanA_body<64>(Alog_m, g_SumM, s_del, s_u, s_bc,
                   (size_t)s*NCHK + cp*2 + half, d, half*TCH);
}

__global__ void __launch_bounds__(128) k_scanA_g(const float* __restrict__ Alog_g)
{
    __shared__ __align__(16) float s_del[TCH*128];
    __shared__ __align__(16) float s_u  [TCH*128];
    __shared__ __align__(16) float s_bc [TCH*32];
    int tid = threadIdx.x;
    int bid = blockIdx.x;
    int s = bid / NCHK, ch = bid - s*NCHK;
    size_t base = (size_t)s*LSEQ + (size_t)ch*TCH;
    stage_tile<128,TCH>(g_dg, g_Ug, g_BCg, base, tid, s_del, s_u, s_bc);
    __syncthreads();
    scanA_body<128>(Alog_g, g_SumG, s_del, s_u, s_bc,
                    (size_t)s*NCHK + ch, tid, 0);
}

// ============ scan phase B: hierarchical prefix (register-staged) ===========
template<int D>
__device__ __forceinline__ void scanB1_body(int t)
{
    const float* Sum = (D == 64) ? g_SumM : g_SumG;
    float* GA = (D == 64) ? g_GAm : g_GAg;
    float* GB = (D == 64) ? g_GBm : g_GBg;
    int n = t & 15;
    int g = (t >> 4) % NGRP;
    int rest = t / (16*NGRP);
    int d = rest % D, s = rest / D;
    const float* p = Sum + (((size_t)s*NCHK + g*GSZ)*D + d)*32 + n;
    float av[GSZ], bv[GSZ];
    #pragma unroll
    for (int c = 0; c < GSZ; c++) {
        bv[c] = p[(size_t)c*D*32];
        av[c] = p[(size_t)c*D*32 + 16];
    }
    float A = 1.f, B = 0.f;
    #pragma unroll
    for (int c = 0; c < GSZ; c++) { A = av[c]*A; B = av[c]*B + bv[c]; }
    size_t gi = (((size_t)s*NGRP + g)*D + d)*16 + n;
    GA[gi] = A; GB[gi] = B;
}
__global__ void __launch_bounds__(256) k_scanB1_m()
{
    int t = blockIdx.x * 256 + threadIdx.x;
    if (t < 4*64*16*NGRP) scanB1_body<64>(t);
}
__global__ void __launch_bounds__(256) k_scanB1_g()
{
    int t = blockIdx.x * 256 + threadIdx.x;
    if (t < 4*128*16*NGRP) scanB1_body<128>(t);
}
template<int D>
__device__ __forceinline__ void scanB2_body(int t)
{
    const float* GA = (D == 64) ? g_GAm : g_GAg;
    const float* GB = (D == 64) ? g_GBm : g_GBg;
    float* GH = (D == 64) ? g_GHm : g_GHg;
    int n = t & 15;
    int d = (t >> 4) % D;
    int s = t / (D*16);
    size_t stride = (size_t)D*16;
    size_t base = ((size_t)s*NGRP*D + d)*16 + n;
    float av[NGRP], bv[NGRP];
    #pragma unroll
    for (int g = 0; g < NGRP; g++) {
        size_t gi = base + (size_t)g*stride;
        av[g] = GA[gi]; bv[g] = GB[gi];
    }
    float P = 0.f;
    #pragma unroll
    for (int g = 0; g < NGRP; g++) {
        GH[base + (size_t)g*stride] = P;
        P = av[g]*P + bv[g];
    }
}
__global__ void __launch_bounds__(256) k_scanB2_m()
{
    int t = blockIdx.x * 256 + threadIdx.x;
    if (t < 4*64*16) scanB2_body<64>(t);
}
__global__ void __launch_bounds__(256) k_scanB2_g()
{
    int t = blockIdx.x * 256 + threadIdx.x;
    if (t < 4*128*16) scanB2_body<128>(t);
}
template<int D>
__device__ __forceinline__ void scanB3_body(int t)
{
    const float* Sum = (D == 64) ? g_SumM : g_SumG;
    const float* GH  = (D == 64) ? g_GHm : g_GHg;
    float* Hin = (D == 64) ? g_HinM : g_HinG;
    int n = t & 15;
    int g = (t >> 4) % NGRP;
    int rest = t / (16*NGRP);
    int d = rest % D, s = rest / D;
    float hin = GH[(((size_t)s*NGRP + g)*D + d)*16 + n];
    const float* p = Sum + (((size_t)s*NCHK + g*GSZ)*D + d)*32 + n;
    float* hp = Hin + (((size_t)s*NCHK + g*GSZ)*D + d)*16 + n;
    float av[GSZ], bv[GSZ];
    #pragma unroll
    for (int c = 0; c < GSZ; c++) {
        bv[c] = p[(size_t)c*D*32];
        av[c] = p[(size_t)c*D*32 + 16];
    }
    #pragma unroll
    for (int c = 0; c < GSZ; c++) {
        hp[(size_t)c*D*16] = hin;
        hin = av[c]*hin + bv[c];
    }
}
__global__ void __launch_bounds__(256) k_scanB3_m()
{
    int t = blockIdx.x * 256 + threadIdx.x;
    if (t < 4*64*16*NGRP) scanB3_body<64>(t);
}
__global__ void __launch_bounds__(256) k_scanB3_g()
{
    int t = blockIdx.x * 256 + threadIdx.x;
    if (t < 4*128*16*NGRP) scanB3_body<128>(t);
}

// ---------------- scan phase C ------------------------------------------------
template<int D>
__device__ __forceinline__ void scanC_body(
    const float* __restrict__ Alog, const float* __restrict__ Dp,
    const float* __restrict__ Hin, float* __restrict__ Y,
    const float* s_del, const float* s_u, const float* s_bc,
    size_t chunkIdx, int d, int off, size_t base)
{
    float Ar[16];
    bool st = loadA(Alog, d, Ar);
    float A0 = Ar[0];
    float h[16];
    const float4* hp = (const float4*)(Hin + (chunkIdx*D + d)*16);
    float4 h0 = hp[0], h1 = hp[1], h2 = hp[2], h3 = hp[3];
    h[0]=h0.x; h[1]=h0.y; h[2]=h0.z; h[3]=h0.w;
    h[4]=h1.x; h[5]=h1.y; h[6]=h1.z; h[7]=h1.w;
    h[8]=h2.x; h[9]=h2.y; h[10]=h2.z; h[11]=h2.w;
    h[12]=h3.x; h[13]=h3.y; h[14]=h3.z; h[15]=h3.w;
    float Dd = Dp[d];
    const float4* bc = (const float4*)s_bc;
    float* yp = Y + (base + off)*D + d;
    #pragma unroll 4
    for (int t = 0; t < TCH; t++) {
        int tt = off + t;
        float del = s_del[tt*D + d];
        float u   = s_u  [tt*D + d];
        float du  = del * u;
        float4 b0 = bc[tt*8+0], b1 = bc[tt*8+1], b2 = bc[tt*8+2], b3 = bc[tt*8+3];
        float4 c0 = bc[tt*8+4], c1 = bc[tt*8+5], c2 = bc[tt*8+6], c3 = bc[tt*8+7];
        float a[16];
        if (st) powers16(__expf(del*A0), a);
        else {
            #pragma unroll
            for (int n = 0; n < 16; n++) a[n] = __expf(del*Ar[n]);
        }
        h[0]=a[0]*h[0]+du*b0.x;  h[1]=a[1]*h[1]+du*b0.y;
        h[2]=a[2]*h[2]+du*b0.z;  h[3]=a[3]*h[3]+du*b0.w;
        h[4]=a[4]*h[4]+du*b1.x;  h[5]=a[5]*h[5]+du*b1.y;
        h[6]=a[6]*h[6]+du*b1.z;  h[7]=a[7]*h[7]+du*b1.w;
        h[8]=a[8]*h[8]+du*b2.x;  h[9]=a[9]*h[9]+du*b2.y;
        h[10]=a[10]*h[10]+du*b2.z; h[11]=a[11]*h[11]+du*b2.w;
        h[12]=a[12]*h[12]+du*b3.x; h[13]=a[13]*h[13]+du*b3.y;
        h[14]=a[14]*h[14]+du*b3.z; h[15]=a[15]*h[15]+du*b3.w;
        float y = Dd*u;
        y += h[0]*c0.x + h[1]*c0.y + h[2]*c0.z + h[3]*c0.w;
        y += h[4]*c1.x + h[5]*c1.y + h[6]*c1.z + h[7]*c1.w;
        y += h[8]*c2.x + h[9]*c2.y + h[10]*c2.z + h[11]*c2.w;
        y += h[12]*c3.x + h[13]*c3.y + h[14]*c3.z + h[15]*c3.w;
        yp[(size_t)t*D] = y;
    }
}

__global__ void __launch_bounds__(128) k_scanC_m(
    const float* __restrict__ Alog_m, const float* __restrict__ Dm)
{
    __shared__ __align__(16) float s_del[2*TCH*64];
    __shared__ __align__(16) float s_u  [2*TCH*64];
    __shared__ __align__(16) float s_bc [2*TCH*32];
    int tid = threadIdx.x;
    int bid = blockIdx.x;
    int s = bid / (NCHK/2), cp = bid - s*(NCHK/2);
    size_t base = (size_t)s*LSEQ + (size_t)cp*(2*TCH);
    stage_tile<64,2*TCH>(g_dm, g_Um, g_BCm, base, tid, s_del, s_u, s_bc);
    __syncthreads();
    int half = tid >> 6, d = tid & 63;
    scanC_body<64>(Alog_m, Dm, g_HinM, g_ym, s_del, s_u, s_bc,
                   (size_t)s*NCHK + cp*2 + half, d, half*TCH, base);
}

__global__ void __launch_bounds__(128) k_scanC_g(
    const float* __restrict__ Alog_g, const float* __restrict__ Dg)
{
    __shared__ __align__(16) float s_del[TCH*128];
    __shared__ __align__(16) float s_u  [TCH*128];
    __shared__ __align__(16) float s_bc [TCH*32];
    int tid = threadIdx.x;
    int bid = blockIdx.x;
    int s = bid / NCHK, ch = bid - s*NCHK;
    size_t base = (size_t)s*LSEQ + (size_t)ch*TCH;
    stage_tile<128,TCH>(g_dg, g_Ug, g_BCg, base, tid, s_del, s_u, s_bc);
    __syncthreads();
    scanC_body<128>(Alog_g, Dg, g_HinG, g_yg, s_del, s_u, s_bc,
                    (size_t)s*NCHK + ch, tid, 0, base);
}

// ---------------- output: o = (mixer ⊙ global) @ Wo^T + bo (packed) ---------
__global__ void __launch_bounds__(256) k_out(
    const float* __restrict__ Wo, const float* __restrict__ bo,
    float* __restrict__ out)
{
    __shared__ __align__(16) float sp[64*132];
    int o = blockIdx.y >> 1, b = blockIdx.y & 1;
    int l0 = blockIdx.x * 64;
    int tid = threadIdx.x;

    int sm = (o == 0) ? b : 2 + b;
    int sg = (o == 0) ? 2 + b : b;
    const float* ym = g_ym + ((size_t)sm*LSEQ + l0)*64;
    const float* zz = g_Z  + ((size_t)sm*LSEQ + l0)*64;
    const float* yg = g_yg + ((size_t)sg*LSEQ + l0)*128;

    for (int i = tid; i < 64*128; i += 256) {
        int t = i >> 7, k = i & 127;
        float m = (k < 64) ? ym[t*64 + k] : zz[t*64 + (k-64)];
        sp[t*132 + k] = m * yg[t*128 + k];
    }
    __syncthreads();

    int tx = tid & 15, ty = tid >> 4;
    int ch0 = tx * 4, t0 = ty * 4;
    u64 acc[4][4];
    #pragma unroll
    for (int i = 0; i < 4; i++)
        #pragma unroll
        for (int j = 0; j < 4; j++) acc[i][j] = 0ull;

    const ulonglong2* p0 = (const ulonglong2*)(sp + (t0+0)*132);
    const ulonglong2* p1 = (const ulonglong2*)(sp + (t0+1)*132);
    const ulonglong2* p2 = (const ulonglong2*)(sp + (t0+2)*132);
    const ulonglong2* p3 = (const ulonglong2*)(sp + (t0+3)*132);
    const ulonglong2* w0 = (const ulonglong2*)(Wo + (ch0+0)*128);
    const ulonglong2* w1 = (const ulonglong2*)(Wo + (ch0+1)*128);
    const ulonglong2* w2 = (const ulonglong2*)(Wo + (ch0+2)*128);
    const ulonglong2* w3 = (const ulonglong2*)(Wo + (ch0+3)*128);
    #pragma unroll 8
    for (int k4 = 0; k4 < 32; k4++) {
        ulonglong2 pv[4] = { p0[k4], p1[k4], p2[k4], p3[k4] };
        ulonglong2 wv[4] = { __ldg(w0+k4), __ldg(w1+k4), __ldg(w2+k4), __ldg(w3+k4) };
        #pragma unroll
        for (int i = 0; i < 4; i++)
            #pragma unroll
            for (int j = 0; j < 4; j++) {
                fma2(acc[i][j], pv[i].x, wv[j].x);
                fma2(acc[i][j], pv[i].y, wv[j].y);
            }
    }
    float* op = out + ((size_t)o*2 + b)*64*LSEQ;
    #pragma unroll
    for (int j = 0; j < 4; j++) {
        float bj = bo[ch0 + j];
        float4 v = { upksum(acc[0][j])+bj, upksum(acc[1][j])+bj,
                     upksum(acc[2][j])+bj, upksum(acc[3][j])+bj };
        *(float4*)(op + (size_t)(ch0+j)*LSEQ + l0 + t0) = v;
    }
}

// -----------------------------------------------------------------------------
extern "C" void kernel_launch(void* const* d_in, const int* in_sizes, int n_in,
                              void* d_out, int out_size)
{
    const float* f1    = (const float*)d_in[0];
    const float* f2    = (const float*)d_in[1];
    const float* Wi    = (const float*)d_in[2];
    const float* bi    = (const float*)d_in[3];
    const float* wcx   = (const float*)d_in[4];
    const float* bcx   = (const float*)d_in[5];
    const float* wcz   = (const float*)d_in[6];
    const float* bcz   = (const float*)d_in[7];
    const float* Wxp_m = (const float*)d_in[8];
    const float* Wdt_m = (const float*)d_in[9];
    const float* bdt_m = (const float*)d_in[10];
    const float* Alog_m= (const float*)d_in[11];
    const float* Dm    = (const float*)d_in[12];
    const float* Wg    = (const float*)d_in[13];
    const float* bg    = (const float*)d_in[14];
    const float* ln_g  = (const float*)d_in[15];
    const float* ln_b  = (const float*)d_in[16];
    const float* wcg   = (const float*)d_in[17];
    const float* bcg   = (const float*)d_in[18];
    const float* Wxp_g = (const float*)d_in[19];
    const float* Wdt_g = (const float*)d_in[20];
    const float* bdt_g = (const float*)d_in[21];
    const float* Alog_g= (const float*)d_in[22];
    const float* Dg    = (const float*)d_in[23];
    const float* Wo    = (const float*)d_in[24];
    const float* bo    = (const float*)d_in[25];
    float* out = (float*)d_out;

    static cudaStream_t s_mix = nullptr;
    static cudaEvent_t ev_fork = nullptr, ev_join = nullptr;
    if (s_mix == nullptr) {
        cudaStreamCreateWithFlags(&s_mix, cudaStreamNonBlocking);
        cudaEventCreateWithFlags(&ev_fork, cudaEventDisableTiming);
        cudaEventCreateWithFlags(&ev_join, cudaEventDisableTiming);
    }

    cudaEventRecord(ev_fork, 0);
    cudaStreamWaitEvent(s_mix, ev_fork, 0);

    // mixer chain (short)
    k_mixer_front <<<dim3(4, LSEQ/64), 128, 0, s_mix>>>(
        f1, f2, Wi, bi, wcx, bcx, wcz, bcz, Wxp_m, Wdt_m, bdt_m);
    k_scanA_m  <<<4*(NCHK/2), 128, 0, s_mix>>>(Alog_m);
    k_scanB1_m <<<(4*64*16*NGRP + 255)/256, 256, 0, s_mix>>>();
    k_scanB2_m <<<(4*64*16 + 255)/256, 256, 0, s_mix>>>();
    k_scanB3_m <<<(4*64*16*NGRP + 255)/256, 256, 0, s_mix>>>();
    k_scanC_m  <<<4*(NCHK/2), 128, 0, s_mix>>>(Alog_m, Dm);
    cudaEventRecord(ev_join, s_mix);

    // global chain (long)
    k_global_front<<<dim3(4, LSEQ/32), 128>>>(
        f1, f2, Wg, bg, ln_g, ln_b, wcg, bcg, Wxp_g, Wdt_g, bdt_g);
    k_scanA_g  <<<4*NCHK, 128>>>(Alog_g);
    k_scanB1_g <<<(4*128*16*NGRP + 255)/256, 256>>>();
    k_scanB2_g <<<(4*128*16 + 255)/256, 256>>>();
    k_scanB3_g <<<(4*128*16*NGRP + 255)/256, 256>>>();
    k_scanC_g  <<<4*NCHK, 128>>>(Alog_g, Dg);

    cudaStreamWaitEvent(0, ev_join, 0);
    k_out <<<dim3(LSEQ/64, 4), 256>>>(Wo, bo, out);
}